// round 5
// baseline (speedup 1.0000x reference)
#include <cuda_runtime.h>
#include <cuda_bf16.h>
#include <math.h>

// ---------------------------------------------------------------------------
// Problem constants (all dims multiples of 128 -> no bounds checks anywhere)
// ---------------------------------------------------------------------------
#define BATCH 8
#define NSEQ  2048
#define HDIM  1024
#define FDIM  4096
#define MTOT  (BATCH * NSEQ)          // 16384 rows

// ---------------------------------------------------------------------------
// Scratch: __device__ globals (allocation-free per harness rules)
// ---------------------------------------------------------------------------
static __device__ float g_ln[(size_t)MTOT * HDIM];            // LN output (reused for LN1 and LN2)
static __device__ float g_q [(size_t)MTOT * HDIM];
static __device__ float g_k [(size_t)MTOT * HDIM];
static __device__ float g_v [(size_t)MTOT * HDIM];
static __device__ float g_x1[(size_t)MTOT * HDIM];            // x + attention (residual 1)
static __device__ float g_s [(size_t)BATCH * NSEQ * NSEQ];    // attention scores / probs
static __device__ float g_h [(size_t)MTOT * FDIM];            // FFN hidden

// ---------------------------------------------------------------------------
// Block reductions (256 threads)
// ---------------------------------------------------------------------------
__device__ __forceinline__ float block_reduce_max(float v) {
    __shared__ float sm[8];
    __syncthreads();  // safe reuse across consecutive calls
    #pragma unroll
    for (int o = 16; o; o >>= 1) v = fmaxf(v, __shfl_xor_sync(0xffffffffu, v, o));
    if ((threadIdx.x & 31) == 0) sm[threadIdx.x >> 5] = v;
    __syncthreads();
    if (threadIdx.x < 32) {
        float w = (threadIdx.x < 8) ? sm[threadIdx.x] : -INFINITY;
        #pragma unroll
        for (int o = 4; o; o >>= 1) w = fmaxf(w, __shfl_xor_sync(0xffffffffu, w, o));
        if (threadIdx.x == 0) sm[0] = w;
    }
    __syncthreads();
    return sm[0];
}

__device__ __forceinline__ float block_reduce_sum(float v) {
    __shared__ float sm[8];
    __syncthreads();
    #pragma unroll
    for (int o = 16; o; o >>= 1) v += __shfl_xor_sync(0xffffffffu, v, o);
    if ((threadIdx.x & 31) == 0) sm[threadIdx.x >> 5] = v;
    __syncthreads();
    if (threadIdx.x < 32) {
        float w = (threadIdx.x < 8) ? sm[threadIdx.x] : 0.0f;
        #pragma unroll
        for (int o = 4; o; o >>= 1) w += __shfl_xor_sync(0xffffffffu, w, o);
        if (threadIdx.x == 0) sm[0] = w;
    }
    __syncthreads();
    return sm[0];
}

// ---------------------------------------------------------------------------
// LayerNorm: 1 block per row of 1024 floats, 256 threads, float4 per thread
// ---------------------------------------------------------------------------
__global__ void __launch_bounds__(256) ln_kernel(
    const float* __restrict__ x, const float* __restrict__ g,
    const float* __restrict__ b, float* __restrict__ y)
{
    const size_t row = blockIdx.x;
    const float4 v = reinterpret_cast<const float4*>(x + row * HDIM)[threadIdx.x];
    float s  = v.x + v.y + v.z + v.w;
    float ss = v.x*v.x + v.y*v.y + v.z*v.z + v.w*v.w;

    __shared__ float sm_s[8], sm_ss[8];
    #pragma unroll
    for (int o = 16; o; o >>= 1) {
        s  += __shfl_xor_sync(0xffffffffu, s,  o);
        ss += __shfl_xor_sync(0xffffffffu, ss, o);
    }
    if ((threadIdx.x & 31) == 0) { sm_s[threadIdx.x >> 5] = s; sm_ss[threadIdx.x >> 5] = ss; }
    __syncthreads();
    if (threadIdx.x < 32) {
        float ws  = (threadIdx.x < 8) ? sm_s [threadIdx.x] : 0.0f;
        float wss = (threadIdx.x < 8) ? sm_ss[threadIdx.x] : 0.0f;
        #pragma unroll
        for (int o = 4; o; o >>= 1) {
            ws  += __shfl_xor_sync(0xffffffffu, ws,  o);
            wss += __shfl_xor_sync(0xffffffffu, wss, o);
        }
        if (threadIdx.x == 0) { sm_s[0] = ws; sm_ss[0] = wss; }
    }
    __syncthreads();

    const float mu  = sm_s[0]  * (1.0f / HDIM);
    const float var = sm_ss[0] * (1.0f / HDIM) - mu * mu;
    const float rs  = rsqrtf(var + 1e-5f);

    const float4 gv = reinterpret_cast<const float4*>(g)[threadIdx.x];
    const float4 bv = reinterpret_cast<const float4*>(b)[threadIdx.x];
    float4 o4;
    o4.x = (v.x - mu) * rs * gv.x + bv.x;
    o4.y = (v.y - mu) * rs * gv.y + bv.y;
    o4.z = (v.z - mu) * rs * gv.z + bv.z;
    o4.w = (v.w - mu) * rs * gv.w + bv.w;
    reinterpret_cast<float4*>(y + row * HDIM)[threadIdx.x] = o4;
}

// ---------------------------------------------------------------------------
// Softmax over rows of length 2048, in place. 1 block per row, 256 threads,
// 8 elements per thread held in registers between passes.
// ---------------------------------------------------------------------------
__global__ void __launch_bounds__(256) softmax_kernel(float* __restrict__ s)
{
    const size_t row = blockIdx.x;                          // 16384 rows
    float4* r = reinterpret_cast<float4*>(s) + row * (NSEQ / 4);
    const int t = threadIdx.x;
    float4 a = r[t];
    float4 c = r[t + 256];
    float vals[8] = {a.x, a.y, a.z, a.w, c.x, c.y, c.z, c.w};

    float m = vals[0];
    #pragma unroll
    for (int i = 1; i < 8; i++) m = fmaxf(m, vals[i]);
    m = block_reduce_max(m);

    float sum = 0.0f;
    #pragma unroll
    for (int i = 0; i < 8; i++) { vals[i] = expf(vals[i] - m); sum += vals[i]; }
    sum = block_reduce_sum(sum);

    const float inv = 1.0f / sum;
    a.x = vals[0]*inv; a.y = vals[1]*inv; a.z = vals[2]*inv; a.w = vals[3]*inv;
    c.x = vals[4]*inv; c.y = vals[5]*inv; c.z = vals[6]*inv; c.w = vals[7]*inv;
    r[t]       = a;
    r[t + 256] = c;
}

// ---------------------------------------------------------------------------
// SGEMM: C[M,N] = alpha * A[M,K] @ op(B) (+ epilogue)
//   TB=false : B is [K,N] row-major
//   TB=true  : B is [N,K] row-major (C = A @ B^T)
// Block tile 128x128, K-tile 8, 256 threads, 8x8 per-thread register tile.
// EPI: 0=none, 1=+res, 2=+bias then exact GELU, 3=+bias +res
// blockIdx.z batches with given element strides.
// ---------------------------------------------------------------------------
template<bool TB, int EPI>
__global__ void __launch_bounds__(256, 2) sgemm_kernel(
    const float* __restrict__ A, const float* __restrict__ B,
    float* __restrict__ C,
    int K, int lda, int ldb, int ldc,
    long long strA, long long strB, long long strC,
    float alpha,
    const float* __restrict__ bias,
    const float* __restrict__ res, long long strRes)
{
    __shared__ __align__(16) float As[8][132];
    __shared__ __align__(16) float Bs[8][132];

    const int bz = blockIdx.z;
    A += strA * bz;
    B += strB * bz;
    C += strC * bz;

    const int bm = blockIdx.y * 128;
    const int bn = blockIdx.x * 128;
    const int tid = threadIdx.x;
    const int tx = tid & 15;          // 16 col-threads
    const int ty = tid >> 4;          // 16 row-threads

    const int lrow = tid >> 1;        // 0..127 (A / NT-B loader row)
    const int lk4  = (tid & 1) * 4;   // 0 or 4
    const int bk   = tid >> 5;        // 0..7   (NN-B loader k)
    const int bn4  = (tid & 31) * 4;  // 0..124

    const float* Aptr = A + (size_t)(bm + lrow) * lda + lk4;
    const float* Bptr = TB ? (B + (size_t)(bn + lrow) * ldb + lk4)
                           : (B + (size_t)bk * ldb + bn + bn4);

    float acc[8][8];
    #pragma unroll
    for (int i = 0; i < 8; i++)
        #pragma unroll
        for (int j = 0; j < 8; j++) acc[i][j] = 0.0f;

    for (int k0 = 0; k0 < K; k0 += 8) {
        const float4 av = *reinterpret_cast<const float4*>(Aptr);
        Aptr += 8;
        float4 bv;
        if (TB) { bv = *reinterpret_cast<const float4*>(Bptr); Bptr += 8; }
        else    { bv = *reinterpret_cast<const float4*>(Bptr); Bptr += (size_t)8 * ldb; }

        __syncthreads();
        As[lk4+0][lrow] = av.x; As[lk4+1][lrow] = av.y;
        As[lk4+2][lrow] = av.z; As[lk4+3][lrow] = av.w;
        if (TB) {
            Bs[lk4+0][lrow] = bv.x; Bs[lk4+1][lrow] = bv.y;
            Bs[lk4+2][lrow] = bv.z; Bs[lk4+3][lrow] = bv.w;
        } else {
            *reinterpret_cast<float4*>(&Bs[bk][bn4]) = bv;
        }
        __syncthreads();

        #pragma unroll
        for (int kk = 0; kk < 8; kk++) {
            const float4 a0 = *reinterpret_cast<const float4*>(&As[kk][ty * 8]);
            const float4 a1 = *reinterpret_cast<const float4*>(&As[kk][ty * 8 + 4]);
            const float4 b0 = *reinterpret_cast<const float4*>(&Bs[kk][tx * 8]);
            const float4 b1 = *reinterpret_cast<const float4*>(&Bs[kk][tx * 8 + 4]);
            const float ar[8] = {a0.x, a0.y, a0.z, a0.w, a1.x, a1.y, a1.z, a1.w};
            const float br[8] = {b0.x, b0.y, b0.z, b0.w, b1.x, b1.y, b1.z, b1.w};
            #pragma unroll
            for (int i = 0; i < 8; i++)
                #pragma unroll
                for (int j = 0; j < 8; j++)
                    acc[i][j] = fmaf(ar[i], br[j], acc[i][j]);
        }
    }

    // Epilogue
    #pragma unroll
    for (int i = 0; i < 8; i++) {
        const int row = bm + ty * 8 + i;
        float* crow = C + (size_t)row * ldc + bn + tx * 8;
        const float* rrow = nullptr;
        if constexpr (EPI == 1 || EPI == 3)
            rrow = res + strRes * blockIdx.z + (size_t)row * ldc + bn + tx * 8;

        #pragma unroll
        for (int j = 0; j < 8; j += 4) {
            float4 o;
            o.x = acc[i][j + 0] * alpha;
            o.y = acc[i][j + 1] * alpha;
            o.z = acc[i][j + 2] * alpha;
            o.w = acc[i][j + 3] * alpha;
            if constexpr (EPI == 2 || EPI == 3) {
                const float4 bb = *reinterpret_cast<const float4*>(&bias[bn + tx * 8 + j]);
                o.x += bb.x; o.y += bb.y; o.z += bb.z; o.w += bb.w;
            }
            if constexpr (EPI == 2) {  // exact GELU: 0.5*x*(1+erf(x/sqrt(2)))
                o.x = 0.5f * o.x * (1.0f + erff(o.x * 0.70710678118654752f));
                o.y = 0.5f * o.y * (1.0f + erff(o.y * 0.70710678118654752f));
                o.z = 0.5f * o.z * (1.0f + erff(o.z * 0.70710678118654752f));
                o.w = 0.5f * o.w * (1.0f + erff(o.w * 0.70710678118654752f));
            }
            if constexpr (EPI == 1 || EPI == 3) {
                const float4 rr = *reinterpret_cast<const float4*>(&rrow[j]);
                o.x += rr.x; o.y += rr.y; o.z += rr.z; o.w += rr.w;
            }
            *reinterpret_cast<float4*>(&crow[j]) = o;
        }
    }
}

// ---------------------------------------------------------------------------
// kernel_launch — inputs per metadata order:
// 0:x 1:ln1_g 2:ln1_b 3:Wq 4:Wk 5:Wv 6:ln2_g 7:ln2_b 8:W1 9:b1 10:W2 11:b2
// ---------------------------------------------------------------------------
extern "C" void kernel_launch(void* const* d_in, const int* /*in_sizes*/, int /*n_in*/,
                              void* d_out, int /*out_size*/)
{
    const float* x     = (const float*)d_in[0];
    const float* ln1_g = (const float*)d_in[1];
    const float* ln1_b = (const float*)d_in[2];
    const float* Wq    = (const float*)d_in[3];
    const float* Wk    = (const float*)d_in[4];
    const float* Wv    = (const float*)d_in[5];
    const float* ln2_g = (const float*)d_in[6];
    const float* ln2_b = (const float*)d_in[7];
    const float* W1    = (const float*)d_in[8];
    const float* b1    = (const float*)d_in[9];
    const float* W2    = (const float*)d_in[10];
    const float* b2    = (const float*)d_in[11];
    float* out = (float*)d_out;

    float *ln, *q, *k, *v, *x1, *s, *h;
    cudaGetSymbolAddress((void**)&ln, g_ln);
    cudaGetSymbolAddress((void**)&q,  g_q);
    cudaGetSymbolAddress((void**)&k,  g_k);
    cudaGetSymbolAddress((void**)&v,  g_v);
    cudaGetSymbolAddress((void**)&x1, g_x1);
    cudaGetSymbolAddress((void**)&s,  g_s);
    cudaGetSymbolAddress((void**)&h,  g_h);

    const long long sNH = (long long)NSEQ * HDIM;   // 2048*1024
    const long long sNN = (long long)NSEQ * NSEQ;   // 2048*2048

    // 1) LN1
    ln_kernel<<<MTOT, 256>>>(x, ln1_g, ln1_b, ln);

    // 2) Q,K,V = ln @ W  (M=16384, N=1024, K=1024)
    {
        dim3 grid(HDIM / 128, MTOT / 128);
        sgemm_kernel<false, 0><<<grid, 256>>>(ln, Wq, q, HDIM, HDIM, HDIM, HDIM,
                                              0, 0, 0, 1.0f, nullptr, nullptr, 0);
        sgemm_kernel<false, 0><<<grid, 256>>>(ln, Wk, k, HDIM, HDIM, HDIM, HDIM,
                                              0, 0, 0, 1.0f, nullptr, nullptr, 0);
        sgemm_kernel<false, 0><<<grid, 256>>>(ln, Wv, v, HDIM, HDIM, HDIM, HDIM,
                                              0, 0, 0, 1.0f, nullptr, nullptr, 0);
    }

    // 3) scores = (Q @ K^T) / 32, batched over 8
    {
        dim3 grid(NSEQ / 128, NSEQ / 128, BATCH);
        sgemm_kernel<true, 0><<<grid, 256>>>(q, k, s, HDIM, HDIM, HDIM, NSEQ,
                                             sNH, sNH, sNN, 0.03125f,
                                             nullptr, nullptr, 0);
    }

    // 4) softmax over last dim (in place)
    softmax_kernel<<<BATCH * NSEQ, 256>>>(s);

    // 5) x1 = x + att @ V, batched
    {
        dim3 grid(HDIM / 128, NSEQ / 128, BATCH);
        sgemm_kernel<false, 1><<<grid, 256>>>(s, v, x1, NSEQ, NSEQ, HDIM, HDIM,
                                              sNN, sNH, sNH, 1.0f,
                                              nullptr, x, sNH);
    }

    // 6) LN2
    ln_kernel<<<MTOT, 256>>>(x1, ln2_g, ln2_b, ln);

    // 7) h = gelu(ln @ W1 + b1)   (M=16384, N=4096, K=1024)
    {
        dim3 grid(FDIM / 128, MTOT / 128);
        sgemm_kernel<false, 2><<<grid, 256>>>(ln, W1, h, HDIM, HDIM, FDIM, FDIM,
                                              0, 0, 0, 1.0f, b1, nullptr, 0);
    }

    // 8) out = x1 + h @ W2 + b2   (M=16384, N=1024, K=4096)
    {
        dim3 grid(HDIM / 128, MTOT / 128);
        sgemm_kernel<false, 3><<<grid, 256>>>(h, W2, out, FDIM, FDIM, HDIM, HDIM,
                                              0, 0, 0, 1.0f, b2, x1, 0);
    }
}

// round 7
// speedup vs baseline: 2.4053x; 2.4053x over previous
#include <cuda_runtime.h>
#include <cuda_fp16.h>
#include <math.h>
#include <stdint.h>

#define BATCH 8
#define NSEQ  2048
#define HDIM  1024
#define FDIM  4096
#define MTOT  (BATCH * NSEQ)

typedef __half  f16;
typedef __half2 f162;

// ---------------- scratch (__device__ globals; allocation-free) ----------------
static __device__ __align__(16) f16   g_lnh[(size_t)MTOT * HDIM];
static __device__ __align__(16) f16   g_lnl[(size_t)MTOT * HDIM];
static __device__ __align__(16) f16   g_qh [(size_t)MTOT * HDIM];
static __device__ __align__(16) f16   g_ql [(size_t)MTOT * HDIM];
static __device__ __align__(16) f16   g_kh [(size_t)MTOT * HDIM];
static __device__ __align__(16) f16   g_kl [(size_t)MTOT * HDIM];
static __device__ __align__(16) f16   g_vh [(size_t)MTOT * HDIM];
static __device__ __align__(16) f16   g_vl [(size_t)MTOT * HDIM];
static __device__ __align__(16) f16   g_vth[(size_t)MTOT * HDIM];
static __device__ __align__(16) f16   g_vtl[(size_t)MTOT * HDIM];
static __device__ __align__(16) float g_s  [(size_t)BATCH * NSEQ * NSEQ];
static __device__ __align__(16) f16   g_ph [(size_t)BATCH * NSEQ * NSEQ];
static __device__ __align__(16) f16   g_pl [(size_t)BATCH * NSEQ * NSEQ];
static __device__ __align__(16) float g_x1 [(size_t)MTOT * HDIM];
static __device__ __align__(16) f16   g_hh [(size_t)MTOT * FDIM];
static __device__ __align__(16) f16   g_hl [(size_t)MTOT * FDIM];
static __device__ __align__(16) f16   g_wqh[(size_t)HDIM * HDIM];
static __device__ __align__(16) f16   g_wql[(size_t)HDIM * HDIM];
static __device__ __align__(16) f16   g_wkh[(size_t)HDIM * HDIM];
static __device__ __align__(16) f16   g_wkl[(size_t)HDIM * HDIM];
static __device__ __align__(16) f16   g_wvh[(size_t)HDIM * HDIM];
static __device__ __align__(16) f16   g_wvl[(size_t)HDIM * HDIM];
static __device__ __align__(16) f16   g_w1h[(size_t)FDIM * HDIM];
static __device__ __align__(16) f16   g_w1l[(size_t)FDIM * HDIM];
static __device__ __align__(16) f16   g_w2h[(size_t)HDIM * FDIM];
static __device__ __align__(16) f16   g_w2l[(size_t)HDIM * FDIM];

// ---------------- helpers ----------------
__device__ __forceinline__ uint32_t smem_u32(const void* p) {
    uint32_t a;
    asm("{ .reg .u64 t; cvta.to.shared.u64 t, %1; cvt.u32.u64 %0, t; }" : "=r"(a) : "l"(p));
    return a;
}
__device__ __forceinline__ void cpa16(uint32_t dst, const f16* src) {
    asm volatile("cp.async.cg.shared.global [%0], [%1], 16;" :: "r"(dst), "l"(src));
}
__device__ __forceinline__ void cp_commit() { asm volatile("cp.async.commit_group;" ::: "memory"); }
__device__ __forceinline__ void ldmA(uint32_t* a, uint32_t addr) {
    asm volatile("ldmatrix.sync.aligned.m8n8.x4.shared.b16 {%0,%1,%2,%3}, [%4];"
                 : "=r"(a[0]), "=r"(a[1]), "=r"(a[2]), "=r"(a[3]) : "r"(addr));
}
__device__ __forceinline__ void mma16816(float* d, const uint32_t* a, const uint32_t* b) {
    asm volatile(
        "mma.sync.aligned.m16n8k16.row.col.f32.f16.f16.f32 "
        "{%0,%1,%2,%3}, {%4,%5,%6,%7}, {%8,%9}, {%0,%1,%2,%3};"
        : "+f"(d[0]), "+f"(d[1]), "+f"(d[2]), "+f"(d[3])
        : "r"(a[0]), "r"(a[1]), "r"(a[2]), "r"(a[3]), "r"(b[0]), "r"(b[1]));
}
__device__ __forceinline__ void split1(float a, f16& h, f16& l) {
    h = __float2half_rn(a);
    l = __float2half_rn(a - __half2float(h));
}
__device__ __forceinline__ float gelu_exact(float x) {
    return 0.5f * x * (1.0f + erff(x * 0.70710678118654752440f));
}

// ---------------------------------------------------------------------------
// split-fp16 mma.sync GEMM: C = alpha*(A @ B^T) (+epilogue)
// A:[M,K] hi/lo, B:[N,K] hi/lo, K-major (ld = K). Block 128x128, kchunk 32,
// 256 thr, warp tile 64x32, fp32 accum = AhBh + AhBl + AlBh.
// EPI: 0 Cf=alpha*acc | 1 split(acc) | 2 Cf=acc+res | 3 split(gelu(acc+bias))
//      4 Cf=acc+bias+res
// smem: 2 buffers x 4 planes x [128 rows x 80B] = 81920 B
// ---------------------------------------------------------------------------
#define PLANE   10240
#define BUFSZ   (4 * PLANE)
#define MM_SMEM (2 * BUFSZ)

template<int EPI>
__global__ void __launch_bounds__(256) mm_kernel(
    const f16* __restrict__ Ah, const f16* __restrict__ Al,
    const f16* __restrict__ Bh, const f16* __restrict__ Bl,
    int K, long long strA, long long strB, long long strC,
    int ldc, float alpha,
    float* __restrict__ Cf, const float* __restrict__ bias,
    const float* __restrict__ res, long long strRes,
    f16* __restrict__ Ch, f16* __restrict__ Cl)
{
    extern __shared__ __align__(16) char smem[];
    const uint32_t su = smem_u32(smem);
    const int tid  = threadIdx.x;
    const int lane = tid & 31;
    const int warp = tid >> 5;
    const int bz   = blockIdx.z;
    const int bm   = blockIdx.y * 128;
    const int bn   = blockIdx.x * 128;

    Ah += (size_t)strA * bz;  Al += (size_t)strA * bz;
    Bh += (size_t)strB * bz;  Bl += (size_t)strB * bz;

    // loader mapping: idx in [0,512): row = idx>>2, 16B-chunk = idx&3
    const int i0 = tid, i1 = tid + 256;
    const int r0l = i0 >> 2, c0l = i0 & 3;
    const int r1l = i1 >> 2, c1l = i1 & 3;
    const uint32_t d0 = (uint32_t)(r0l * 80 + c0l * 16);
    const uint32_t d1 = (uint32_t)(r1l * 80 + c1l * 16);
    const size_t gA0 = (size_t)(bm + r0l) * K + c0l * 8;
    const size_t gA1 = (size_t)(bm + r1l) * K + c1l * 8;
    const size_t gB0 = (size_t)(bn + r0l) * K + c0l * 8;
    const size_t gB1 = (size_t)(bn + r1l) * K + c1l * 8;

    const int nch = K >> 5;

    // warp tile: 2 (m) x 4 (n)
    const int wm = (warp & 1) * 64;
    const int wn = (warp >> 1) * 32;

    float acc[4][4][4];
    #pragma unroll
    for (int i = 0; i < 4; i++)
        #pragma unroll
        for (int j = 0; j < 4; j++)
            #pragma unroll
            for (int r = 0; r < 4; r++) acc[i][j][r] = 0.0f;

    // A-frag ldmatrix address components (per mtile, per ks)
    const int arow = lane & 15;
    const int acol = (lane >> 4) * 16;      // bytes
    // B-frag LDS address components (per ntile, per ks)
    const int brow = lane >> 2;
    const int bcol = (lane & 3) * 4;        // bytes

    // prologue: load chunk 0 into buf 0
    {
        const size_t k0 = 0;
        uint32_t b = su;
        cpa16(b + d0,              Ah + gA0 + k0);  cpa16(b + d1,              Ah + gA1 + k0);
        cpa16(b + PLANE + d0,      Al + gA0 + k0);  cpa16(b + PLANE + d1,      Al + gA1 + k0);
        cpa16(b + 2*PLANE + d0,    Bh + gB0 + k0);  cpa16(b + 2*PLANE + d1,    Bh + gB1 + k0);
        cpa16(b + 3*PLANE + d0,    Bl + gB0 + k0);  cpa16(b + 3*PLANE + d1,    Bl + gB1 + k0);
        cp_commit();
    }

    for (int c = 0; c < nch; c++) {
        if (c + 1 < nch) {
            const size_t k0 = (size_t)(c + 1) << 5;
            uint32_t b = su + ((c + 1) & 1) * BUFSZ;
            cpa16(b + d0,           Ah + gA0 + k0);  cpa16(b + d1,           Ah + gA1 + k0);
            cpa16(b + PLANE + d0,   Al + gA0 + k0);  cpa16(b + PLANE + d1,   Al + gA1 + k0);
            cpa16(b + 2*PLANE + d0, Bh + gB0 + k0);  cpa16(b + 2*PLANE + d1, Bh + gB1 + k0);
            cpa16(b + 3*PLANE + d0, Bl + gB0 + k0);  cpa16(b + 3*PLANE + d1, Bl + gB1 + k0);
            cp_commit();
            asm volatile("cp.async.wait_group 1;" ::: "memory");
        } else {
            asm volatile("cp.async.wait_group 0;" ::: "memory");
        }
        __syncthreads();

        const uint32_t bb = su + (c & 1) * BUFSZ;
        const char*    sb = smem + (c & 1) * BUFSZ;

        #pragma unroll
        for (int ks = 0; ks < 2; ks++) {
            uint32_t aH[4][4], aL[4][4], bH[4][2], bL[4][2];
            #pragma unroll
            for (int i = 0; i < 4; i++) {
                const uint32_t ao = (uint32_t)((wm + i * 16 + arow) * 80 + ks * 32 + acol);
                ldmA(aH[i], bb + ao);
                ldmA(aL[i], bb + PLANE + ao);
            }
            #pragma unroll
            for (int j = 0; j < 4; j++) {
                const int bo = (wn + j * 8 + brow) * 80 + ks * 32 + bcol;
                bH[j][0] = *reinterpret_cast<const uint32_t*>(sb + 2*PLANE + bo);
                bH[j][1] = *reinterpret_cast<const uint32_t*>(sb + 2*PLANE + bo + 16);
                bL[j][0] = *reinterpret_cast<const uint32_t*>(sb + 3*PLANE + bo);
                bL[j][1] = *reinterpret_cast<const uint32_t*>(sb + 3*PLANE + bo + 16);
            }
            #pragma unroll
            for (int i = 0; i < 4; i++)
                #pragma unroll
                for (int j = 0; j < 4; j++) mma16816(acc[i][j], aH[i], bH[j]);
            #pragma unroll
            for (int i = 0; i < 4; i++)
                #pragma unroll
                for (int j = 0; j < 4; j++) mma16816(acc[i][j], aH[i], bL[j]);
            #pragma unroll
            for (int i = 0; i < 4; i++)
                #pragma unroll
                for (int j = 0; j < 4; j++) mma16816(acc[i][j], aL[i], bH[j]);
        }
        __syncthreads();
    }

    // -------- epilogue --------
    #pragma unroll
    for (int i = 0; i < 4; i++) {
        #pragma unroll
        for (int j = 0; j < 4; j++) {
            const int r0 = bm + wm + i * 16 + (lane >> 2);
            const int r1 = r0 + 8;
            const int cc = bn + wn + j * 8 + (lane & 3) * 2;
            float v[4] = {acc[i][j][0], acc[i][j][1], acc[i][j][2], acc[i][j][3]};

            if constexpr (EPI == 0) {
                v[0] *= alpha; v[1] *= alpha; v[2] *= alpha; v[3] *= alpha;
            }
            if constexpr (EPI == 3 || EPI == 4) {
                const float2 bbv = *reinterpret_cast<const float2*>(bias + cc);
                v[0] += bbv.x; v[1] += bbv.y; v[2] += bbv.x; v[3] += bbv.y;
            }
            if constexpr (EPI == 3) {
                v[0] = gelu_exact(v[0]); v[1] = gelu_exact(v[1]);
                v[2] = gelu_exact(v[2]); v[3] = gelu_exact(v[3]);
            }
            if constexpr (EPI == 2 || EPI == 4) {
                const float* rp = res + (size_t)strRes * bz;
                const float2 q0 = *reinterpret_cast<const float2*>(rp + (size_t)r0 * ldc + cc);
                const float2 q1 = *reinterpret_cast<const float2*>(rp + (size_t)r1 * ldc + cc);
                v[0] += q0.x; v[1] += q0.y; v[2] += q1.x; v[3] += q1.y;
            }

            if constexpr (EPI == 0 || EPI == 2 || EPI == 4) {
                float* cp0 = Cf + (size_t)strC * bz + (size_t)r0 * ldc + cc;
                float* cp1 = Cf + (size_t)strC * bz + (size_t)r1 * ldc + cc;
                *reinterpret_cast<float2*>(cp0) = make_float2(v[0], v[1]);
                *reinterpret_cast<float2*>(cp1) = make_float2(v[2], v[3]);
            } else {
                f16 h0, l0, h1, l1;
                f162 hh2, ll2;
                split1(v[0], h0, l0); split1(v[1], h1, l1);
                hh2 = __halves2half2(h0, h1); ll2 = __halves2half2(l0, l1);
                *reinterpret_cast<f162*>(Ch + (size_t)strC * bz + (size_t)r0 * ldc + cc) = hh2;
                *reinterpret_cast<f162*>(Cl + (size_t)strC * bz + (size_t)r0 * ldc + cc) = ll2;
                split1(v[2], h0, l0); split1(v[3], h1, l1);
                hh2 = __halves2half2(h0, h1); ll2 = __halves2half2(l0, l1);
                *reinterpret_cast<f162*>(Ch + (size_t)strC * bz + (size_t)r1 * ldc + cc) = hh2;
                *reinterpret_cast<f162*>(Cl + (size_t)strC * bz + (size_t)r1 * ldc + cc) = ll2;
            }
        }
    }
}

// ---------------- LayerNorm -> split fp16 ----------------
__global__ void __launch_bounds__(256) ln_split_kernel(
    const float* __restrict__ x, const float* __restrict__ g,
    const float* __restrict__ b, f16* __restrict__ yh, f16* __restrict__ yl)
{
    const size_t row = blockIdx.x;
    const float4 v = reinterpret_cast<const float4*>(x + row * HDIM)[threadIdx.x];
    float s  = v.x + v.y + v.z + v.w;
    float ss = v.x * v.x + v.y * v.y + v.z * v.z + v.w * v.w;

    __shared__ float sm_s[8], sm_ss[8];
    #pragma unroll
    for (int o = 16; o; o >>= 1) {
        s  += __shfl_xor_sync(0xffffffffu, s,  o);
        ss += __shfl_xor_sync(0xffffffffu, ss, o);
    }
    if ((threadIdx.x & 31) == 0) { sm_s[threadIdx.x >> 5] = s; sm_ss[threadIdx.x >> 5] = ss; }
    __syncthreads();
    if (threadIdx.x < 32) {
        float ws  = (threadIdx.x < 8) ? sm_s [threadIdx.x] : 0.0f;
        float wss = (threadIdx.x < 8) ? sm_ss[threadIdx.x] : 0.0f;
        #pragma unroll
        for (int o = 4; o; o >>= 1) {
            ws  += __shfl_xor_sync(0xffffffffu, ws,  o);
            wss += __shfl_xor_sync(0xffffffffu, wss, o);
        }
        if (threadIdx.x == 0) { sm_s[0] = ws; sm_ss[0] = wss; }
    }
    __syncthreads();

    const float mu  = sm_s[0]  * (1.0f / HDIM);
    const float var = sm_ss[0] * (1.0f / HDIM) - mu * mu;
    const float rs  = rsqrtf(var + 1e-5f);

    const float4 gv = reinterpret_cast<const float4*>(g)[threadIdx.x];
    const float4 bv = reinterpret_cast<const float4*>(b)[threadIdx.x];
    const float o0 = (v.x - mu) * rs * gv.x + bv.x;
    const float o1 = (v.y - mu) * rs * gv.y + bv.y;
    const float o2 = (v.z - mu) * rs * gv.z + bv.z;
    const float o3 = (v.w - mu) * rs * gv.w + bv.w;

    f16 h0, l0, h1, l1;
    const size_t off = row * HDIM + (size_t)threadIdx.x * 4;
    split1(o0, h0, l0); split1(o1, h1, l1);
    *reinterpret_cast<f162*>(yh + off)     = __halves2half2(h0, h1);
    *reinterpret_cast<f162*>(yl + off)     = __halves2half2(l0, l1);
    split1(o2, h0, l0); split1(o3, h1, l1);
    *reinterpret_cast<f162*>(yh + off + 2) = __halves2half2(h0, h1);
    *reinterpret_cast<f162*>(yl + off + 2) = __halves2half2(l0, l1);
}

// ---------------- Softmax (2048) fp32 -> split fp16 ----------------
__global__ void __launch_bounds__(256) softmax_split_kernel(
    const float* __restrict__ s, f16* __restrict__ ph, f16* __restrict__ pl)
{
    const size_t row = blockIdx.x;
    const float4* r = reinterpret_cast<const float4*>(s) + row * (NSEQ / 4);
    const int t = threadIdx.x;
    const float4 a = r[t];
    const float4 c = r[t + 256];
    float vals[8] = {a.x, a.y, a.z, a.w, c.x, c.y, c.z, c.w};

    __shared__ float sm[8];
    float m = vals[0];
    #pragma unroll
    for (int i = 1; i < 8; i++) m = fmaxf(m, vals[i]);
    #pragma unroll
    for (int o = 16; o; o >>= 1) m = fmaxf(m, __shfl_xor_sync(0xffffffffu, m, o));
    if ((t & 31) == 0) sm[t >> 5] = m;
    __syncthreads();
    if (t < 32) {
        float w = (t < 8) ? sm[t] : -INFINITY;
        #pragma unroll
        for (int o = 4; o; o >>= 1) w = fmaxf(w, __shfl_xor_sync(0xffffffffu, w, o));
        if (t == 0) sm[0] = w;
    }
    __syncthreads();
    m = sm[0];
    __syncthreads();

    float sum = 0.0f;
    #pragma unroll
    for (int i = 0; i < 8; i++) { vals[i] = expf(vals[i] - m); sum += vals[i]; }
    #pragma unroll
    for (int o = 16; o; o >>= 1) sum += __shfl_xor_sync(0xffffffffu, sum, o);
    if ((t & 31) == 0) sm[t >> 5] = sum;
    __syncthreads();
    if (t < 32) {
        float w = (t < 8) ? sm[t] : 0.0f;
        #pragma unroll
        for (int o = 4; o; o >>= 1) w += __shfl_xor_sync(0xffffffffu, w, o);
        if (t == 0) sm[0] = w;
    }
    __syncthreads();
    const float inv = 1.0f / sm[0];

    const size_t base = row * NSEQ;
    f16 h0, l0, h1, l1;
    #pragma unroll
    for (int half = 0; half < 2; half++) {
        const size_t off = base + (size_t)(t + half * 256) * 4;
        const int v0 = half * 4;
        split1(vals[v0 + 0] * inv, h0, l0); split1(vals[v0 + 1] * inv, h1, l1);
        *reinterpret_cast<f162*>(ph + off)     = __halves2half2(h0, h1);
        *reinterpret_cast<f162*>(pl + off)     = __halves2half2(l0, l1);
        split1(vals[v0 + 2] * inv, h0, l0); split1(vals[v0 + 3] * inv, h1, l1);
        *reinterpret_cast<f162*>(ph + off + 2) = __halves2half2(h0, h1);
        *reinterpret_cast<f162*>(pl + off + 2) = __halves2half2(l0, l1);
    }
}

// ---------------- fp32 W[R,C] -> split-fp16 W^T[C,R] ----------------
__global__ void __launch_bounds__(256) wsplit_t_kernel(
    const float* __restrict__ W, int R, int C,
    f16* __restrict__ Th, f16* __restrict__ Tl)
{
    __shared__ float t[32][33];
    const int bx = blockIdx.x * 32;   // C
    const int by = blockIdx.y * 32;   // R
    const int tx = threadIdx.x, ty = threadIdx.y;
    #pragma unroll
    for (int i = 0; i < 4; i++)
        t[ty + i * 8][tx] = W[(size_t)(by + ty + i * 8) * C + bx + tx];
    __syncthreads();
    #pragma unroll
    for (int i = 0; i < 4; i++) {
        const float v = t[tx][ty + i * 8];
        const size_t o = (size_t)(bx + ty + i * 8) * R + by + tx;
        f16 h, l;
        split1(v, h, l);
        Th[o] = h;
        Tl[o] = l;
    }
}

// ---------------- V hi/lo [B][NSEQ,H] -> Vt hi/lo [B][H,NSEQ] ----------------
__global__ void __launch_bounds__(256) vtrans_kernel(
    const f16* __restrict__ vh, const f16* __restrict__ vl,
    f16* __restrict__ vth, f16* __restrict__ vtl)
{
    const int z = blockIdx.z;
    const int b = z >> 1;
    const bool lo = z & 1;
    const f16* src = (lo ? vl : vh) + (size_t)b * NSEQ * HDIM;
    f16* dst       = (lo ? vtl : vth) + (size_t)b * HDIM * NSEQ;

    __shared__ f16 t[32][33];
    const int bx = blockIdx.x * 32;   // H
    const int by = blockIdx.y * 32;   // NSEQ
    const int tx = threadIdx.x, ty = threadIdx.y;
    #pragma unroll
    for (int i = 0; i < 4; i++)
        t[ty + i * 8][tx] = src[(size_t)(by + ty + i * 8) * HDIM + bx + tx];
    __syncthreads();
    #pragma unroll
    for (int i = 0; i < 4; i++)
        dst[(size_t)(bx + ty + i * 8) * NSEQ + by + tx] = t[tx][ty + i * 8];
}

// ---------------------------------------------------------------------------
// kernel_launch — inputs: 0:x 1:ln1_g 2:ln1_b 3:Wq 4:Wk 5:Wv 6:ln2_g 7:ln2_b
//                         8:W1 9:b1 10:W2 11:b2
// ---------------------------------------------------------------------------
extern "C" void kernel_launch(void* const* d_in, const int*, int,
                              void* d_out, int)
{
    const float* x     = (const float*)d_in[0];
    const float* ln1_g = (const float*)d_in[1];
    const float* ln1_b = (const float*)d_in[2];
    const float* Wq    = (const float*)d_in[3];
    const float* Wk    = (const float*)d_in[4];
    const float* Wv    = (const float*)d_in[5];
    const float* ln2_g = (const float*)d_in[6];
    const float* ln2_b = (const float*)d_in[7];
    const float* W1    = (const float*)d_in[8];
    const float* b1    = (const float*)d_in[9];
    const float* W2    = (const float*)d_in[10];
    const float* b2    = (const float*)d_in[11];
    float* out = (float*)d_out;

    f16 *lnh, *lnl, *qh, *ql, *kh, *kl, *vh, *vl, *vth, *vtl, *ph, *pl, *hh, *hl;
    f16 *wqh, *wql, *wkh, *wkl, *wvh, *wvl, *w1h, *w1l, *w2h, *w2l;
    float *s, *x1;
    cudaGetSymbolAddress((void**)&lnh, g_lnh); cudaGetSymbolAddress((void**)&lnl, g_lnl);
    cudaGetSymbolAddress((void**)&qh, g_qh);   cudaGetSymbolAddress((void**)&ql, g_ql);
    cudaGetSymbolAddress((void**)&kh, g_kh);   cudaGetSymbolAddress((void**)&kl, g_kl);
    cudaGetSymbolAddress((void**)&vh, g_vh);   cudaGetSymbolAddress((void**)&vl, g_vl);
    cudaGetSymbolAddress((void**)&vth, g_vth); cudaGetSymbolAddress((void**)&vtl, g_vtl);
    cudaGetSymbolAddress((void**)&ph, g_ph);   cudaGetSymbolAddress((void**)&pl, g_pl);
    cudaGetSymbolAddress((void**)&hh, g_hh);   cudaGetSymbolAddress((void**)&hl, g_hl);
    cudaGetSymbolAddress((void**)&wqh, g_wqh); cudaGetSymbolAddress((void**)&wql, g_wql);
    cudaGetSymbolAddress((void**)&wkh, g_wkh); cudaGetSymbolAddress((void**)&wkl, g_wkl);
    cudaGetSymbolAddress((void**)&wvh, g_wvh); cudaGetSymbolAddress((void**)&wvl, g_wvl);
    cudaGetSymbolAddress((void**)&w1h, g_w1h); cudaGetSymbolAddress((void**)&w1l, g_w1l);
    cudaGetSymbolAddress((void**)&w2h, g_w2h); cudaGetSymbolAddress((void**)&w2l, g_w2l);
    cudaGetSymbolAddress((void**)&s, g_s);     cudaGetSymbolAddress((void**)&x1, g_x1);

    cudaFuncSetAttribute(mm_kernel<0>, cudaFuncAttributeMaxDynamicSharedMemorySize, MM_SMEM);
    cudaFuncSetAttribute(mm_kernel<1>, cudaFuncAttributeMaxDynamicSharedMemorySize, MM_SMEM);
    cudaFuncSetAttribute(mm_kernel<2>, cudaFuncAttributeMaxDynamicSharedMemorySize, MM_SMEM);
    cudaFuncSetAttribute(mm_kernel<3>, cudaFuncAttributeMaxDynamicSharedMemorySize, MM_SMEM);
    cudaFuncSetAttribute(mm_kernel<4>, cudaFuncAttributeMaxDynamicSharedMemorySize, MM_SMEM);

    const long long sNH = (long long)NSEQ * HDIM;
    const long long sNN = (long long)NSEQ * NSEQ;

    // weight transpose + split
    { dim3 b(32, 8);
      wsplit_t_kernel<<<dim3(HDIM/32, HDIM/32), b>>>(Wq, HDIM, HDIM, wqh, wql);
      wsplit_t_kernel<<<dim3(HDIM/32, HDIM/32), b>>>(Wk, HDIM, HDIM, wkh, wkl);
      wsplit_t_kernel<<<dim3(HDIM/32, HDIM/32), b>>>(Wv, HDIM, HDIM, wvh, wvl);
      wsplit_t_kernel<<<dim3(FDIM/32, HDIM/32), b>>>(W1, HDIM, FDIM, w1h, w1l);
      wsplit_t_kernel<<<dim3(HDIM/32, FDIM/32), b>>>(W2, FDIM, HDIM, w2h, w2l); }

    // LN1 -> split
    ln_split_kernel<<<MTOT, 256>>>(x, ln1_g, ln1_b, lnh, lnl);

    // QKV (M=16384, N=1024, K=1024), split outputs
    { dim3 g(HDIM/128, MTOT/128);
      mm_kernel<1><<<g, 256, MM_SMEM>>>(lnh, lnl, wqh, wql, HDIM, 0, 0, 0, HDIM,
                                        1.0f, nullptr, nullptr, nullptr, 0, qh, ql);
      mm_kernel<1><<<g, 256, MM_SMEM>>>(lnh, lnl, wkh, wkl, HDIM, 0, 0, 0, HDIM,
                                        1.0f, nullptr, nullptr, nullptr, 0, kh, kl);
      mm_kernel<1><<<g, 256, MM_SMEM>>>(lnh, lnl, wvh, wvl, HDIM, 0, 0, 0, HDIM,
                                        1.0f, nullptr, nullptr, nullptr, 0, vh, vl); }

    // scores = (Q @ K^T)/32, fp32
    { dim3 g(NSEQ/128, NSEQ/128, BATCH);
      mm_kernel<0><<<g, 256, MM_SMEM>>>(qh, ql, kh, kl, HDIM, sNH, sNH, sNN, NSEQ,
                                        0.03125f, s, nullptr, nullptr, 0, nullptr, nullptr); }

    // softmax -> split probs
    softmax_split_kernel<<<BATCH * NSEQ, 256>>>(s, ph, pl);

    // V^T per batch (hi/lo planes)
    vtrans_kernel<<<dim3(HDIM/32, NSEQ/32, BATCH * 2), dim3(32, 8)>>>(vh, vl, vth, vtl);

    // x1 = x + P @ V  (A=P [NSEQ,NSEQ], B=Vt [HDIM,NSEQ])
    { dim3 g(HDIM/128, NSEQ/128, BATCH);
      mm_kernel<2><<<g, 256, MM_SMEM>>>(ph, pl, vth, vtl, NSEQ, sNN, sNH, sNH, HDIM,
                                        1.0f, x1, nullptr, x, sNH, nullptr, nullptr); }

    // LN2 -> split
    ln_split_kernel<<<MTOT, 256>>>(x1, ln2_g, ln2_b, lnh, lnl);

    // h = gelu(ln @ W1 + b1), split outputs (M=16384, N=4096, K=1024)
    { dim3 g(FDIM/128, MTOT/128);
      mm_kernel<3><<<g, 256, MM_SMEM>>>(lnh, lnl, w1h, w1l, HDIM, 0, 0, 0, FDIM,
                                        1.0f, nullptr, b1, nullptr, 0, hh, hl); }

    // out = x1 + h @ W2 + b2 (M=16384, N=1024, K=4096)
    { dim3 g(HDIM/128, MTOT/128);
      mm_kernel<4><<<g, 256, MM_SMEM>>>(hh, hl, w2h, w2l, FDIM, 0, 0, 0, HDIM,
                                        1.0f, out, b2, x1, 0, nullptr, nullptr); }
}

// round 8
// speedup vs baseline: 2.8202x; 1.1725x over previous
#include <cuda_runtime.h>
#include <cuda_fp16.h>
#include <math.h>
#include <stdint.h>

#define BATCH 8
#define NSEQ  2048
#define HDIM  1024
#define FDIM  4096
#define MTOT  (BATCH * NSEQ)

typedef __half  f16;
typedef __half2 f162;

// ---------------- scratch (__device__ globals; allocation-free) ----------------
static __device__ __align__(16) f16   g_lnh[(size_t)MTOT * HDIM];
static __device__ __align__(16) f16   g_lnl[(size_t)MTOT * HDIM];
static __device__ __align__(16) f16   g_qh [(size_t)MTOT * HDIM];
static __device__ __align__(16) f16   g_ql [(size_t)MTOT * HDIM];
static __device__ __align__(16) f16   g_kh [(size_t)MTOT * HDIM];
static __device__ __align__(16) f16   g_kl [(size_t)MTOT * HDIM];
static __device__ __align__(16) f16   g_vh [(size_t)MTOT * HDIM];
static __device__ __align__(16) f16   g_vl [(size_t)MTOT * HDIM];
static __device__ __align__(16) f16   g_vth[(size_t)MTOT * HDIM];
static __device__ __align__(16) f16   g_vtl[(size_t)MTOT * HDIM];
static __device__ __align__(16) float g_s  [(size_t)BATCH * NSEQ * NSEQ];
static __device__ __align__(16) f16   g_ph [(size_t)BATCH * NSEQ * NSEQ];
static __device__ __align__(16) f16   g_pl [(size_t)BATCH * NSEQ * NSEQ];
static __device__ __align__(16) float g_x1 [(size_t)MTOT * HDIM];
static __device__ __align__(16) f16   g_hh [(size_t)MTOT * FDIM];
static __device__ __align__(16) f16   g_hl [(size_t)MTOT * FDIM];
static __device__ __align__(16) f16   g_wqh[(size_t)HDIM * HDIM];
static __device__ __align__(16) f16   g_wql[(size_t)HDIM * HDIM];
static __device__ __align__(16) f16   g_wkh[(size_t)HDIM * HDIM];
static __device__ __align__(16) f16   g_wkl[(size_t)HDIM * HDIM];
static __device__ __align__(16) f16   g_wvh[(size_t)HDIM * HDIM];
static __device__ __align__(16) f16   g_wvl[(size_t)HDIM * HDIM];
static __device__ __align__(16) f16   g_w1h[(size_t)FDIM * HDIM];
static __device__ __align__(16) f16   g_w1l[(size_t)FDIM * HDIM];
static __device__ __align__(16) f16   g_w2h[(size_t)HDIM * FDIM];
static __device__ __align__(16) f16   g_w2l[(size_t)HDIM * FDIM];

// ---------------- helpers ----------------
__device__ __forceinline__ uint32_t smem_u32(const void* p) {
    uint32_t a;
    asm("{ .reg .u64 t; cvta.to.shared.u64 t, %1; cvt.u32.u64 %0, t; }" : "=r"(a) : "l"(p));
    return a;
}
__device__ __forceinline__ void cpa16(uint32_t dst, const f16* src) {
    asm volatile("cp.async.cg.shared.global [%0], [%1], 16;" :: "r"(dst), "l"(src));
}
__device__ __forceinline__ void cp_commit() { asm volatile("cp.async.commit_group;" ::: "memory"); }
__device__ __forceinline__ void ldm4(uint32_t* a, uint32_t addr) {
    asm volatile("ldmatrix.sync.aligned.m8n8.x4.shared.b16 {%0,%1,%2,%3}, [%4];"
                 : "=r"(a[0]), "=r"(a[1]), "=r"(a[2]), "=r"(a[3]) : "r"(addr));
}
__device__ __forceinline__ void mma16816(float* d, const uint32_t* a, const uint32_t* b) {
    asm volatile(
        "mma.sync.aligned.m16n8k16.row.col.f32.f16.f16.f32 "
        "{%0,%1,%2,%3}, {%4,%5,%6,%7}, {%8,%9}, {%0,%1,%2,%3};"
        : "+f"(d[0]), "+f"(d[1]), "+f"(d[2]), "+f"(d[3])
        : "r"(a[0]), "r"(a[1]), "r"(a[2]), "r"(a[3]), "r"(b[0]), "r"(b[1]));
}
__device__ __forceinline__ void split1(float a, f16& h, f16& l) {
    h = __float2half_rn(a);
    l = __float2half_rn(a - __half2float(h));
}
__device__ __forceinline__ float gelu_exact(float x) {
    return 0.5f * x * (1.0f + erff(x * 0.70710678118654752440f));
}

// ---------------------------------------------------------------------------
// split-fp16 mma.sync GEMM: C = alpha*(A @ B^T) (+epilogue)
// A:[M,K] hi/lo, B:[N,K] hi/lo, K-major. Block 128x128, kchunk 32, 256 thr,
// warp tile 64x32, fp32 accum = AhBh + AhBl + AlBh.
// 2 CTAs/SM (128-reg cap) + ldmatrix for B + sequential-plane loop.
// EPI: 0 Cf=alpha*acc | 1 split(acc) | 2 Cf=acc+res | 3 split(gelu(acc+bias))
//      4 Cf=acc+bias+res
// ---------------------------------------------------------------------------
#define PLANE   10240
#define BUFSZ   (4 * PLANE)
#define MM_SMEM (2 * BUFSZ)

template<int EPI>
__global__ void __launch_bounds__(256, 2) mm_kernel(
    const f16* __restrict__ Ah, const f16* __restrict__ Al,
    const f16* __restrict__ Bh, const f16* __restrict__ Bl,
    int K, long long strA, long long strB, long long strC,
    int ldc, float alpha,
    float* __restrict__ Cf, const float* __restrict__ bias,
    const float* __restrict__ res, long long strRes,
    f16* __restrict__ Ch, f16* __restrict__ Cl)
{
    extern __shared__ __align__(16) char smem[];
    const uint32_t su = smem_u32(smem);
    const int tid  = threadIdx.x;
    const int lane = tid & 31;
    const int warp = tid >> 5;
    const int bz   = blockIdx.z;
    const int bm   = blockIdx.y * 128;
    const int bn   = blockIdx.x * 128;

    Ah += (size_t)strA * bz;  Al += (size_t)strA * bz;
    Bh += (size_t)strB * bz;  Bl += (size_t)strB * bz;

    // loader mapping: idx in [0,512): row = idx>>2, 16B-chunk = idx&3
    const int i0 = tid, i1 = tid + 256;
    const int r0l = i0 >> 2, c0l = i0 & 3;
    const int r1l = i1 >> 2, c1l = i1 & 3;
    const uint32_t d0 = (uint32_t)(r0l * 80 + c0l * 16);
    const uint32_t d1 = (uint32_t)(r1l * 80 + c1l * 16);
    const size_t gA0 = (size_t)(bm + r0l) * K + c0l * 8;
    const size_t gA1 = (size_t)(bm + r1l) * K + c1l * 8;
    const size_t gB0 = (size_t)(bn + r0l) * K + c0l * 8;
    const size_t gB1 = (size_t)(bn + r1l) * K + c1l * 8;

    const int nch = K >> 5;

    // warp tile: 2 (m) x 4 (n)
    const int wm = (warp & 1) * 64;
    const int wn = (warp >> 1) * 32;

    float acc[4][4][4];
    #pragma unroll
    for (int i = 0; i < 4; i++)
        #pragma unroll
        for (int j = 0; j < 4; j++)
            #pragma unroll
            for (int r = 0; r < 4; r++) acc[i][j][r] = 0.0f;

    // A ldmatrix lane address components
    const int arow = lane & 15;
    const int acol = (lane >> 4) * 16;               // bytes
    // B ldmatrix lane address components: ntile j = p*2 + (lane>>4), row = lane&7... see below
    const int bg   = lane >> 3;                      // 0..3 (matrix group)
    const int br   = lane & 7;
    const uint32_t boff = (uint32_t)(((bg >> 1) * 8 + br) * 80 + (bg & 1) * 16);

    // prologue: load chunk 0 into buf 0
    {
        uint32_t b = su;
        cpa16(b + d0,           Ah + gA0);  cpa16(b + d1,           Ah + gA1);
        cpa16(b + PLANE + d0,   Al + gA0);  cpa16(b + PLANE + d1,   Al + gA1);
        cpa16(b + 2*PLANE + d0, Bh + gB0);  cpa16(b + 2*PLANE + d1, Bh + gB1);
        cpa16(b + 3*PLANE + d0, Bl + gB0);  cpa16(b + 3*PLANE + d1, Bl + gB1);
        cp_commit();
    }

    for (int c = 0; c < nch; c++) {
        if (c + 1 < nch) {
            const size_t k0 = (size_t)(c + 1) << 5;
            uint32_t b = su + ((c + 1) & 1) * BUFSZ;
            cpa16(b + d0,           Ah + gA0 + k0);  cpa16(b + d1,           Ah + gA1 + k0);
            cpa16(b + PLANE + d0,   Al + gA0 + k0);  cpa16(b + PLANE + d1,   Al + gA1 + k0);
            cpa16(b + 2*PLANE + d0, Bh + gB0 + k0);  cpa16(b + 2*PLANE + d1, Bh + gB1 + k0);
            cpa16(b + 3*PLANE + d0, Bl + gB0 + k0);  cpa16(b + 3*PLANE + d1, Bl + gB1 + k0);
            cp_commit();
            asm volatile("cp.async.wait_group 1;" ::: "memory");
        } else {
            asm volatile("cp.async.wait_group 0;" ::: "memory");
        }
        __syncthreads();

        const uint32_t bb = su + (c & 1) * BUFSZ;

        #pragma unroll
        for (int ks = 0; ks < 2; ks++) {
            uint32_t a[4][4], bH[4][2], bL[4][2];
            // A hi
            #pragma unroll
            for (int i = 0; i < 4; i++)
                ldm4(a[i], bb + (uint32_t)((wm + i * 16 + arow) * 80 + ks * 32 + acol));
            // B hi (2 x ldmatrix.x4 -> 4 ntiles)
            #pragma unroll
            for (int p = 0; p < 2; p++) {
                uint32_t r[4];
                ldm4(r, bb + 2*PLANE + (uint32_t)((wn + p * 16) * 80 + ks * 32) + boff);
                bH[p*2+0][0] = r[0]; bH[p*2+0][1] = r[1];
                bH[p*2+1][0] = r[2]; bH[p*2+1][1] = r[3];
            }
            #pragma unroll
            for (int i = 0; i < 4; i++)
                #pragma unroll
                for (int j = 0; j < 4; j++) mma16816(acc[i][j], a[i], bH[j]);
            // B lo
            #pragma unroll
            for (int p = 0; p < 2; p++) {
                uint32_t r[4];
                ldm4(r, bb + 3*PLANE + (uint32_t)((wn + p * 16) * 80 + ks * 32) + boff);
                bL[p*2+0][0] = r[0]; bL[p*2+0][1] = r[1];
                bL[p*2+1][0] = r[2]; bL[p*2+1][1] = r[3];
            }
            #pragma unroll
            for (int i = 0; i < 4; i++)
                #pragma unroll
                for (int j = 0; j < 4; j++) mma16816(acc[i][j], a[i], bL[j]);
            // A lo (reuse a regs)
            #pragma unroll
            for (int i = 0; i < 4; i++)
                ldm4(a[i], bb + PLANE + (uint32_t)((wm + i * 16 + arow) * 80 + ks * 32 + acol));
            #pragma unroll
            for (int i = 0; i < 4; i++)
                #pragma unroll
                for (int j = 0; j < 4; j++) mma16816(acc[i][j], a[i], bH[j]);
        }
        __syncthreads();
    }

    // -------- epilogue --------
    #pragma unroll
    for (int i = 0; i < 4; i++) {
        #pragma unroll
        for (int j = 0; j < 4; j++) {
            const int r0 = bm + wm + i * 16 + (lane >> 2);
            const int r1 = r0 + 8;
            const int cc = bn + wn + j * 8 + (lane & 3) * 2;
            float v[4] = {acc[i][j][0], acc[i][j][1], acc[i][j][2], acc[i][j][3]};

            if constexpr (EPI == 0) {
                v[0] *= alpha; v[1] *= alpha; v[2] *= alpha; v[3] *= alpha;
            }
            if constexpr (EPI == 3 || EPI == 4) {
                const float2 bbv = *reinterpret_cast<const float2*>(bias + cc);
                v[0] += bbv.x; v[1] += bbv.y; v[2] += bbv.x; v[3] += bbv.y;
            }
            if constexpr (EPI == 3) {
                v[0] = gelu_exact(v[0]); v[1] = gelu_exact(v[1]);
                v[2] = gelu_exact(v[2]); v[3] = gelu_exact(v[3]);
            }
            if constexpr (EPI == 2 || EPI == 4) {
                const float* rp = res + (size_t)strRes * bz;
                const float2 q0 = *reinterpret_cast<const float2*>(rp + (size_t)r0 * ldc + cc);
                const float2 q1 = *reinterpret_cast<const float2*>(rp + (size_t)r1 * ldc + cc);
                v[0] += q0.x; v[1] += q0.y; v[2] += q1.x; v[3] += q1.y;
            }

            if constexpr (EPI == 0 || EPI == 2 || EPI == 4) {
                float* cp0 = Cf + (size_t)strC * bz + (size_t)r0 * ldc + cc;
                float* cp1 = Cf + (size_t)strC * bz + (size_t)r1 * ldc + cc;
                *reinterpret_cast<float2*>(cp0) = make_float2(v[0], v[1]);
                *reinterpret_cast<float2*>(cp1) = make_float2(v[2], v[3]);
            } else {
                f16 h0, l0, h1, l1;
                split1(v[0], h0, l0); split1(v[1], h1, l1);
                *reinterpret_cast<f162*>(Ch + (size_t)strC * bz + (size_t)r0 * ldc + cc) = __halves2half2(h0, h1);
                *reinterpret_cast<f162*>(Cl + (size_t)strC * bz + (size_t)r0 * ldc + cc) = __halves2half2(l0, l1);
                split1(v[2], h0, l0); split1(v[3], h1, l1);
                *reinterpret_cast<f162*>(Ch + (size_t)strC * bz + (size_t)r1 * ldc + cc) = __halves2half2(h0, h1);
                *reinterpret_cast<f162*>(Cl + (size_t)strC * bz + (size_t)r1 * ldc + cc) = __halves2half2(l0, l1);
            }
        }
    }
}

// ---------------- LayerNorm -> split fp16 ----------------
__global__ void __launch_bounds__(256) ln_split_kernel(
    const float* __restrict__ x, const float* __restrict__ g,
    const float* __restrict__ b, f16* __restrict__ yh, f16* __restrict__ yl)
{
    const size_t row = blockIdx.x;
    const float4 v = reinterpret_cast<const float4*>(x + row * HDIM)[threadIdx.x];
    float s  = v.x + v.y + v.z + v.w;
    float ss = v.x * v.x + v.y * v.y + v.z * v.z + v.w * v.w;

    __shared__ float sm_s[8], sm_ss[8];
    #pragma unroll
    for (int o = 16; o; o >>= 1) {
        s  += __shfl_xor_sync(0xffffffffu, s,  o);
        ss += __shfl_xor_sync(0xffffffffu, ss, o);
    }
    if ((threadIdx.x & 31) == 0) { sm_s[threadIdx.x >> 5] = s; sm_ss[threadIdx.x >> 5] = ss; }
    __syncthreads();
    if (threadIdx.x < 32) {
        float ws  = (threadIdx.x < 8) ? sm_s [threadIdx.x] : 0.0f;
        float wss = (threadIdx.x < 8) ? sm_ss[threadIdx.x] : 0.0f;
        #pragma unroll
        for (int o = 4; o; o >>= 1) {
            ws  += __shfl_xor_sync(0xffffffffu, ws,  o);
            wss += __shfl_xor_sync(0xffffffffu, wss, o);
        }
        if (threadIdx.x == 0) { sm_s[0] = ws; sm_ss[0] = wss; }
    }
    __syncthreads();

    const float mu  = sm_s[0]  * (1.0f / HDIM);
    const float var = sm_ss[0] * (1.0f / HDIM) - mu * mu;
    const float rs  = rsqrtf(var + 1e-5f);

    const float4 gv = reinterpret_cast<const float4*>(g)[threadIdx.x];
    const float4 bv = reinterpret_cast<const float4*>(b)[threadIdx.x];
    const float o0 = (v.x - mu) * rs * gv.x + bv.x;
    const float o1 = (v.y - mu) * rs * gv.y + bv.y;
    const float o2 = (v.z - mu) * rs * gv.z + bv.z;
    const float o3 = (v.w - mu) * rs * gv.w + bv.w;

    f16 h0, l0, h1, l1;
    const size_t off = row * HDIM + (size_t)threadIdx.x * 4;
    split1(o0, h0, l0); split1(o1, h1, l1);
    *reinterpret_cast<f162*>(yh + off)     = __halves2half2(h0, h1);
    *reinterpret_cast<f162*>(yl + off)     = __halves2half2(l0, l1);
    split1(o2, h0, l0); split1(o3, h1, l1);
    *reinterpret_cast<f162*>(yh + off + 2) = __halves2half2(h0, h1);
    *reinterpret_cast<f162*>(yl + off + 2) = __halves2half2(l0, l1);
}

// ---------------- Softmax (2048) fp32 -> split fp16 ----------------
__global__ void __launch_bounds__(256) softmax_split_kernel(
    const float* __restrict__ s, f16* __restrict__ ph, f16* __restrict__ pl)
{
    const size_t row = blockIdx.x;
    const float4* r = reinterpret_cast<const float4*>(s) + row * (NSEQ / 4);
    const int t = threadIdx.x;
    const float4 a = r[t];
    const float4 c = r[t + 256];
    float vals[8] = {a.x, a.y, a.z, a.w, c.x, c.y, c.z, c.w};

    __shared__ float sm[8];
    float m = vals[0];
    #pragma unroll
    for (int i = 1; i < 8; i++) m = fmaxf(m, vals[i]);
    #pragma unroll
    for (int o = 16; o; o >>= 1) m = fmaxf(m, __shfl_xor_sync(0xffffffffu, m, o));
    if ((t & 31) == 0) sm[t >> 5] = m;
    __syncthreads();
    if (t < 32) {
        float w = (t < 8) ? sm[t] : -INFINITY;
        #pragma unroll
        for (int o = 4; o; o >>= 1) w = fmaxf(w, __shfl_xor_sync(0xffffffffu, w, o));
        if (t == 0) sm[0] = w;
    }
    __syncthreads();
    m = sm[0];
    __syncthreads();

    float sum = 0.0f;
    #pragma unroll
    for (int i = 0; i < 8; i++) { vals[i] = expf(vals[i] - m); sum += vals[i]; }
    #pragma unroll
    for (int o = 16; o; o >>= 1) sum += __shfl_xor_sync(0xffffffffu, sum, o);
    if ((t & 31) == 0) sm[t >> 5] = sum;
    __syncthreads();
    if (t < 32) {
        float w = (t < 8) ? sm[t] : 0.0f;
        #pragma unroll
        for (int o = 4; o; o >>= 1) w += __shfl_xor_sync(0xffffffffu, w, o);
        if (t == 0) sm[0] = w;
    }
    __syncthreads();
    const float inv = 1.0f / sm[0];

    const size_t base = row * NSEQ;
    f16 h0, l0, h1, l1;
    #pragma unroll
    for (int half = 0; half < 2; half++) {
        const size_t off = base + (size_t)(t + half * 256) * 4;
        const int v0 = half * 4;
        split1(vals[v0 + 0] * inv, h0, l0); split1(vals[v0 + 1] * inv, h1, l1);
        *reinterpret_cast<f162*>(ph + off)     = __halves2half2(h0, h1);
        *reinterpret_cast<f162*>(pl + off)     = __halves2half2(l0, l1);
        split1(vals[v0 + 2] * inv, h0, l0); split1(vals[v0 + 3] * inv, h1, l1);
        *reinterpret_cast<f162*>(ph + off + 2) = __halves2half2(h0, h1);
        *reinterpret_cast<f162*>(pl + off + 2) = __halves2half2(l0, l1);
    }
}

// ---------------- fp32 W[R,C] -> split-fp16 W^T[C,R] ----------------
__global__ void __launch_bounds__(256) wsplit_t_kernel(
    const float* __restrict__ W, int R, int C,
    f16* __restrict__ Th, f16* __restrict__ Tl)
{
    __shared__ float t[32][33];
    const int bx = blockIdx.x * 32;   // C
    const int by = blockIdx.y * 32;   // R
    const int tx = threadIdx.x, ty = threadIdx.y;
    #pragma unroll
    for (int i = 0; i < 4; i++)
        t[ty + i * 8][tx] = W[(size_t)(by + ty + i * 8) * C + bx + tx];
    __syncthreads();
    #pragma unroll
    for (int i = 0; i < 4; i++) {
        const float v = t[tx][ty + i * 8];
        const size_t o = (size_t)(bx + ty + i * 8) * R + by + tx;
        f16 h, l;
        split1(v, h, l);
        Th[o] = h;
        Tl[o] = l;
    }
}

// ---------------- V hi/lo [B][NSEQ,H] -> Vt hi/lo [B][H,NSEQ] ----------------
__global__ void __launch_bounds__(256) vtrans_kernel(
    const f16* __restrict__ vh, const f16* __restrict__ vl,
    f16* __restrict__ vth, f16* __restrict__ vtl)
{
    const int z = blockIdx.z;
    const int b = z >> 1;
    const bool lo = z & 1;
    const f16* src = (lo ? vl : vh) + (size_t)b * NSEQ * HDIM;
    f16* dst       = (lo ? vtl : vth) + (size_t)b * HDIM * NSEQ;

    __shared__ f16 t[32][33];
    const int bx = blockIdx.x * 32;   // H
    const int by = blockIdx.y * 32;   // NSEQ
    const int tx = threadIdx.x, ty = threadIdx.y;
    #pragma unroll
    for (int i = 0; i < 4; i++)
        t[ty + i * 8][tx] = src[(size_t)(by + ty + i * 8) * HDIM + bx + tx];
    __syncthreads();
    #pragma unroll
    for (int i = 0; i < 4; i++)
        dst[(size_t)(bx + ty + i * 8) * NSEQ + by + tx] = t[tx][ty + i * 8];
}

// ---------------------------------------------------------------------------
// kernel_launch — inputs: 0:x 1:ln1_g 2:ln1_b 3:Wq 4:Wk 5:Wv 6:ln2_g 7:ln2_b
//                         8:W1 9:b1 10:W2 11:b2
// ---------------------------------------------------------------------------
extern "C" void kernel_launch(void* const* d_in, const int*, int,
                              void* d_out, int)
{
    const float* x     = (const float*)d_in[0];
    const float* ln1_g = (const float*)d_in[1];
    const float* ln1_b = (const float*)d_in[2];
    const float* Wq    = (const float*)d_in[3];
    const float* Wk    = (const float*)d_in[4];
    const float* Wv    = (const float*)d_in[5];
    const float* ln2_g = (const float*)d_in[6];
    const float* ln2_b = (const float*)d_in[7];
    const float* W1    = (const float*)d_in[8];
    const float* b1    = (const float*)d_in[9];
    const float* W2    = (const float*)d_in[10];
    const float* b2    = (const float*)d_in[11];
    float* out = (float*)d_out;

    f16 *lnh, *lnl, *qh, *ql, *kh, *kl, *vh, *vl, *vth, *vtl, *ph, *pl, *hh, *hl;
    f16 *wqh, *wql, *wkh, *wkl, *wvh, *wvl, *w1h, *w1l, *w2h, *w2l;
    float *s, *x1;
    cudaGetSymbolAddress((void**)&lnh, g_lnh); cudaGetSymbolAddress((void**)&lnl, g_lnl);
    cudaGetSymbolAddress((void**)&qh, g_qh);   cudaGetSymbolAddress((void**)&ql, g_ql);
    cudaGetSymbolAddress((void**)&kh, g_kh);   cudaGetSymbolAddress((void**)&kl, g_kl);
    cudaGetSymbolAddress((void**)&vh, g_vh);   cudaGetSymbolAddress((void**)&vl, g_vl);
    cudaGetSymbolAddress((void**)&vth, g_vth); cudaGetSymbolAddress((void**)&vtl, g_vtl);
    cudaGetSymbolAddress((void**)&ph, g_ph);   cudaGetSymbolAddress((void**)&pl, g_pl);
    cudaGetSymbolAddress((void**)&hh, g_hh);   cudaGetSymbolAddress((void**)&hl, g_hl);
    cudaGetSymbolAddress((void**)&wqh, g_wqh); cudaGetSymbolAddress((void**)&wql, g_wql);
    cudaGetSymbolAddress((void**)&wkh, g_wkh); cudaGetSymbolAddress((void**)&wkl, g_wkl);
    cudaGetSymbolAddress((void**)&wvh, g_wvh); cudaGetSymbolAddress((void**)&wvl, g_wvl);
    cudaGetSymbolAddress((void**)&w1h, g_w1h); cudaGetSymbolAddress((void**)&w1l, g_w1l);
    cudaGetSymbolAddress((void**)&w2h, g_w2h); cudaGetSymbolAddress((void**)&w2l, g_w2l);
    cudaGetSymbolAddress((void**)&s, g_s);     cudaGetSymbolAddress((void**)&x1, g_x1);

    cudaFuncSetAttribute(mm_kernel<0>, cudaFuncAttributeMaxDynamicSharedMemorySize, MM_SMEM);
    cudaFuncSetAttribute(mm_kernel<1>, cudaFuncAttributeMaxDynamicSharedMemorySize, MM_SMEM);
    cudaFuncSetAttribute(mm_kernel<2>, cudaFuncAttributeMaxDynamicSharedMemorySize, MM_SMEM);
    cudaFuncSetAttribute(mm_kernel<3>, cudaFuncAttributeMaxDynamicSharedMemorySize, MM_SMEM);
    cudaFuncSetAttribute(mm_kernel<4>, cudaFuncAttributeMaxDynamicSharedMemorySize, MM_SMEM);

    const long long sNH = (long long)NSEQ * HDIM;
    const long long sNN = (long long)NSEQ * NSEQ;

    // weight transpose + split
    { dim3 b(32, 8);
      wsplit_t_kernel<<<dim3(HDIM/32, HDIM/32), b>>>(Wq, HDIM, HDIM, wqh, wql);
      wsplit_t_kernel<<<dim3(HDIM/32, HDIM/32), b>>>(Wk, HDIM, HDIM, wkh, wkl);
      wsplit_t_kernel<<<dim3(HDIM/32, HDIM/32), b>>>(Wv, HDIM, HDIM, wvh, wvl);
      wsplit_t_kernel<<<dim3(FDIM/32, HDIM/32), b>>>(W1, HDIM, FDIM, w1h, w1l);
      wsplit_t_kernel<<<dim3(HDIM/32, FDIM/32), b>>>(W2, FDIM, HDIM, w2h, w2l); }

    // LN1 -> split
    ln_split_kernel<<<MTOT, 256>>>(x, ln1_g, ln1_b, lnh, lnl);

    // QKV (M=16384, N=1024, K=1024), split outputs
    { dim3 g(HDIM/128, MTOT/128);
      mm_kernel<1><<<g, 256, MM_SMEM>>>(lnh, lnl, wqh, wql, HDIM, 0, 0, 0, HDIM,
                                        1.0f, nullptr, nullptr, nullptr, 0, qh, ql);
      mm_kernel<1><<<g, 256, MM_SMEM>>>(lnh, lnl, wkh, wkl, HDIM, 0, 0, 0, HDIM,
                                        1.0f, nullptr, nullptr, nullptr, 0, kh, kl);
      mm_kernel<1><<<g, 256, MM_SMEM>>>(lnh, lnl, wvh, wvl, HDIM, 0, 0, 0, HDIM,
                                        1.0f, nullptr, nullptr, nullptr, 0, vh, vl); }

    // scores = (Q @ K^T)/32, fp32
    { dim3 g(NSEQ/128, NSEQ/128, BATCH);
      mm_kernel<0><<<g, 256, MM_SMEM>>>(qh, ql, kh, kl, HDIM, sNH, sNH, sNN, NSEQ,
                                        0.03125f, s, nullptr, nullptr, 0, nullptr, nullptr); }

    // softmax -> split probs
    softmax_split_kernel<<<BATCH * NSEQ, 256>>>(s, ph, pl);

    // V^T per batch (hi/lo planes)
    vtrans_kernel<<<dim3(HDIM/32, NSEQ/32, BATCH * 2), dim3(32, 8)>>>(vh, vl, vth, vtl);

    // x1 = x + P @ V  (A=P [NSEQ,NSEQ], B=Vt [HDIM,NSEQ])
    { dim3 g(HDIM/128, NSEQ/128, BATCH);
      mm_kernel<2><<<g, 256, MM_SMEM>>>(ph, pl, vth, vtl, NSEQ, sNN, sNH, sNH, HDIM,
                                        1.0f, x1, nullptr, x, sNH, nullptr, nullptr); }

    // LN2 -> split
    ln_split_kernel<<<MTOT, 256>>>(x1, ln2_g, ln2_b, lnh, lnl);

    // h = gelu(ln @ W1 + b1), split outputs (M=16384, N=4096, K=1024)
    { dim3 g(FDIM/128, MTOT/128);
      mm_kernel<3><<<g, 256, MM_SMEM>>>(lnh, lnl, w1h, w1l, HDIM, 0, 0, 0, FDIM,
                                        1.0f, nullptr, b1, nullptr, 0, hh, hl); }

    // out = x1 + h @ W2 + b2 (M=16384, N=1024, K=4096)
    { dim3 g(HDIM/128, MTOT/128);
      mm_kernel<4><<<g, 256, MM_SMEM>>>(hh, hl, w2h, w2l, FDIM, 0, 0, 0, HDIM,
                                        1.0f, out, b2, x1, 0, nullptr, nullptr); }
}

// round 9
// speedup vs baseline: 3.9033x; 1.3840x over previous
#include <cuda_runtime.h>
#include <cuda_fp16.h>
#include <math.h>
#include <stdint.h>

#define BATCH 8
#define NSEQ  2048
#define HDIM  1024
#define FDIM  4096
#define MTOT  (BATCH * NSEQ)

typedef __half  f16;
typedef __half2 f162;

// ---------------- scratch (__device__ globals; allocation-free) ----------------
static __device__ __align__(16) f16   g_lnh[(size_t)MTOT * HDIM];   // LN out (hi only)
static __device__ __align__(16) f16   g_qh [(size_t)MTOT * HDIM];   // Q (hi only)
static __device__ __align__(16) f16   g_kh [(size_t)MTOT * HDIM];   // K hi/lo (B operand)
static __device__ __align__(16) f16   g_kl [(size_t)MTOT * HDIM];
static __device__ __align__(16) f16   g_vh [(size_t)MTOT * HDIM];   // V hi/lo (B operand)
static __device__ __align__(16) f16   g_vl [(size_t)MTOT * HDIM];
static __device__ __align__(16) f16   g_vth[(size_t)MTOT * HDIM];   // V^T hi/lo
static __device__ __align__(16) f16   g_vtl[(size_t)MTOT * HDIM];
static __device__ __align__(16) float g_s  [(size_t)BATCH * NSEQ * NSEQ];
static __device__ __align__(16) f16   g_ph [(size_t)BATCH * NSEQ * NSEQ];  // probs (hi only)
static __device__ __align__(16) float g_x1 [(size_t)MTOT * HDIM];
static __device__ __align__(16) f16   g_hh [(size_t)MTOT * FDIM];   // FFN hidden (hi only)
static __device__ __align__(16) f16   g_wqh[(size_t)HDIM * HDIM];
static __device__ __align__(16) f16   g_wql[(size_t)HDIM * HDIM];
static __device__ __align__(16) f16   g_wkh[(size_t)HDIM * HDIM];
static __device__ __align__(16) f16   g_wkl[(size_t)HDIM * HDIM];
static __device__ __align__(16) f16   g_wvh[(size_t)HDIM * HDIM];
static __device__ __align__(16) f16   g_wvl[(size_t)HDIM * HDIM];
static __device__ __align__(16) f16   g_w1h[(size_t)FDIM * HDIM];
static __device__ __align__(16) f16   g_w1l[(size_t)FDIM * HDIM];
static __device__ __align__(16) f16   g_w2h[(size_t)HDIM * FDIM];
static __device__ __align__(16) f16   g_w2l[(size_t)HDIM * FDIM];

// ---------------- helpers ----------------
__device__ __forceinline__ uint32_t smem_u32(const void* p) {
    uint32_t a;
    asm("{ .reg .u64 t; cvta.to.shared.u64 t, %1; cvt.u32.u64 %0, t; }" : "=r"(a) : "l"(p));
    return a;
}
__device__ __forceinline__ void cpa16(uint32_t dst, const f16* src) {
    asm volatile("cp.async.cg.shared.global [%0], [%1], 16;" :: "r"(dst), "l"(src));
}
__device__ __forceinline__ void cp_commit() { asm volatile("cp.async.commit_group;" ::: "memory"); }
__device__ __forceinline__ void ldm4(uint32_t* a, uint32_t addr) {
    asm volatile("ldmatrix.sync.aligned.m8n8.x4.shared.b16 {%0,%1,%2,%3}, [%4];"
                 : "=r"(a[0]), "=r"(a[1]), "=r"(a[2]), "=r"(a[3]) : "r"(addr));
}
__device__ __forceinline__ void mma16816(float* d, const uint32_t* a, const uint32_t* b) {
    asm volatile(
        "mma.sync.aligned.m16n8k16.row.col.f32.f16.f16.f32 "
        "{%0,%1,%2,%3}, {%4,%5,%6,%7}, {%8,%9}, {%0,%1,%2,%3};"
        : "+f"(d[0]), "+f"(d[1]), "+f"(d[2]), "+f"(d[3])
        : "r"(a[0]), "r"(a[1]), "r"(a[2]), "r"(a[3]), "r"(b[0]), "r"(b[1]));
}
__device__ __forceinline__ void split1(float a, f16& h, f16& l) {
    h = __float2half_rn(a);
    l = __float2half_rn(a - __half2float(h));
}
__device__ __forceinline__ float gelu_exact(float x) {
    return 0.5f * x * (1.0f + erff(x * 0.70710678118654752440f));
}

// ---------------------------------------------------------------------------
// 2-term split-fp16 mma.sync GEMM: C = alpha*(A @ B^T) (+epilogue)
// A:[M,K] hi only; B:[N,K] hi/lo. fp32 accum = Ah·Bh + Ah·Bl.
// Block 128x128, kchunk 32, 256 thr, warp tile 64x32, 2 CTAs/SM.
// smem: 2 stages x 3 planes x (128 rows x 80B) = 61440 B.
// EPI: 0 Cf=alpha*acc | 1 Ch,Cl=split(acc) | 2 Cf=acc+res |
//      3 Ch=hi(gelu(acc+bias)) | 4 Cf=acc+bias+res | 5 Ch=hi(acc)
// ---------------------------------------------------------------------------
#define PLANE   10240
#define BUFSZ   (3 * PLANE)
#define MM_SMEM (2 * BUFSZ)

template<int EPI>
__global__ void __launch_bounds__(256, 2) mm_kernel(
    const f16* __restrict__ Ah,
    const f16* __restrict__ Bh, const f16* __restrict__ Bl,
    int K, long long strA, long long strB, long long strC,
    int ldc, float alpha,
    float* __restrict__ Cf, const float* __restrict__ bias,
    const float* __restrict__ res, long long strRes,
    f16* __restrict__ Ch, f16* __restrict__ Cl)
{
    extern __shared__ __align__(16) char smem[];
    const uint32_t su = smem_u32(smem);
    const int tid  = threadIdx.x;
    const int lane = tid & 31;
    const int warp = tid >> 5;
    const int bz   = blockIdx.z;
    const int bm   = blockIdx.y * 128;
    const int bn   = blockIdx.x * 128;

    Ah += (size_t)strA * bz;
    Bh += (size_t)strB * bz;  Bl += (size_t)strB * bz;

    // loader mapping: idx in [0,512): row = idx>>2, 16B-chunk = idx&3
    const int i0 = tid, i1 = tid + 256;
    const int r0l = i0 >> 2, c0l = i0 & 3;
    const int r1l = i1 >> 2, c1l = i1 & 3;
    const uint32_t d0 = (uint32_t)(r0l * 80 + c0l * 16);
    const uint32_t d1 = (uint32_t)(r1l * 80 + c1l * 16);
    const size_t gA0 = (size_t)(bm + r0l) * K + c0l * 8;
    const size_t gA1 = (size_t)(bm + r1l) * K + c1l * 8;
    const size_t gB0 = (size_t)(bn + r0l) * K + c0l * 8;
    const size_t gB1 = (size_t)(bn + r1l) * K + c1l * 8;

    const int nch = K >> 5;

    // warp tile: 2 (m) x 4 (n)
    const int wm = (warp & 1) * 64;
    const int wn = (warp >> 1) * 32;

    float acc[4][4][4];
    #pragma unroll
    for (int i = 0; i < 4; i++)
        #pragma unroll
        for (int j = 0; j < 4; j++)
            #pragma unroll
            for (int r = 0; r < 4; r++) acc[i][j][r] = 0.0f;

    // A ldmatrix lane address components
    const int arow = lane & 15;
    const int acol = (lane >> 4) * 16;               // bytes
    // B ldmatrix lane address components
    const int bg   = lane >> 3;                      // 0..3 (matrix group)
    const int br   = lane & 7;
    const uint32_t boff = (uint32_t)(((bg >> 1) * 8 + br) * 80 + (bg & 1) * 16);

    // prologue: chunk 0 -> buf 0
    {
        uint32_t b = su;
        cpa16(b + d0,           Ah + gA0);  cpa16(b + d1,           Ah + gA1);
        cpa16(b + PLANE + d0,   Bh + gB0);  cpa16(b + PLANE + d1,   Bh + gB1);
        cpa16(b + 2*PLANE + d0, Bl + gB0);  cpa16(b + 2*PLANE + d1, Bl + gB1);
        cp_commit();
    }

    for (int c = 0; c < nch; c++) {
        if (c + 1 < nch) {
            const size_t k0 = (size_t)(c + 1) << 5;
            uint32_t b = su + ((c + 1) & 1) * BUFSZ;
            cpa16(b + d0,           Ah + gA0 + k0);  cpa16(b + d1,           Ah + gA1 + k0);
            cpa16(b + PLANE + d0,   Bh + gB0 + k0);  cpa16(b + PLANE + d1,   Bh + gB1 + k0);
            cpa16(b + 2*PLANE + d0, Bl + gB0 + k0);  cpa16(b + 2*PLANE + d1, Bl + gB1 + k0);
            cp_commit();
            asm volatile("cp.async.wait_group 1;" ::: "memory");
        } else {
            asm volatile("cp.async.wait_group 0;" ::: "memory");
        }
        __syncthreads();

        const uint32_t bb = su + (c & 1) * BUFSZ;

        #pragma unroll
        for (int ks = 0; ks < 2; ks++) {
            uint32_t a[4][4], bH[4][2], bL[4][2];
            #pragma unroll
            for (int i = 0; i < 4; i++)
                ldm4(a[i], bb + (uint32_t)((wm + i * 16 + arow) * 80 + ks * 32 + acol));
            #pragma unroll
            for (int p = 0; p < 2; p++) {
                uint32_t r[4];
                ldm4(r, bb + PLANE + (uint32_t)((wn + p * 16) * 80 + ks * 32) + boff);
                bH[p*2+0][0] = r[0]; bH[p*2+0][1] = r[1];
                bH[p*2+1][0] = r[2]; bH[p*2+1][1] = r[3];
            }
            #pragma unroll
            for (int i = 0; i < 4; i++)
                #pragma unroll
                for (int j = 0; j < 4; j++) mma16816(acc[i][j], a[i], bH[j]);
            #pragma unroll
            for (int p = 0; p < 2; p++) {
                uint32_t r[4];
                ldm4(r, bb + 2*PLANE + (uint32_t)((wn + p * 16) * 80 + ks * 32) + boff);
                bL[p*2+0][0] = r[0]; bL[p*2+0][1] = r[1];
                bL[p*2+1][0] = r[2]; bL[p*2+1][1] = r[3];
            }
            #pragma unroll
            for (int i = 0; i < 4; i++)
                #pragma unroll
                for (int j = 0; j < 4; j++) mma16816(acc[i][j], a[i], bL[j]);
        }
        __syncthreads();
    }

    // -------- epilogue --------
    #pragma unroll
    for (int i = 0; i < 4; i++) {
        #pragma unroll
        for (int j = 0; j < 4; j++) {
            const int r0 = bm + wm + i * 16 + (lane >> 2);
            const int r1 = r0 + 8;
            const int cc = bn + wn + j * 8 + (lane & 3) * 2;
            float v[4] = {acc[i][j][0], acc[i][j][1], acc[i][j][2], acc[i][j][3]};

            if constexpr (EPI == 0) {
                v[0] *= alpha; v[1] *= alpha; v[2] *= alpha; v[3] *= alpha;
            }
            if constexpr (EPI == 3 || EPI == 4) {
                const float2 bbv = *reinterpret_cast<const float2*>(bias + cc);
                v[0] += bbv.x; v[1] += bbv.y; v[2] += bbv.x; v[3] += bbv.y;
            }
            if constexpr (EPI == 3) {
                v[0] = gelu_exact(v[0]); v[1] = gelu_exact(v[1]);
                v[2] = gelu_exact(v[2]); v[3] = gelu_exact(v[3]);
            }
            if constexpr (EPI == 2 || EPI == 4) {
                const float* rp = res + (size_t)strRes * bz;
                const float2 q0 = *reinterpret_cast<const float2*>(rp + (size_t)r0 * ldc + cc);
                const float2 q1 = *reinterpret_cast<const float2*>(rp + (size_t)r1 * ldc + cc);
                v[0] += q0.x; v[1] += q0.y; v[2] += q1.x; v[3] += q1.y;
            }

            if constexpr (EPI == 0 || EPI == 2 || EPI == 4) {
                float* cp0 = Cf + (size_t)strC * bz + (size_t)r0 * ldc + cc;
                float* cp1 = Cf + (size_t)strC * bz + (size_t)r1 * ldc + cc;
                *reinterpret_cast<float2*>(cp0) = make_float2(v[0], v[1]);
                *reinterpret_cast<float2*>(cp1) = make_float2(v[2], v[3]);
            } else if constexpr (EPI == 1) {
                f16 h0, l0, h1, l1;
                split1(v[0], h0, l0); split1(v[1], h1, l1);
                *reinterpret_cast<f162*>(Ch + (size_t)strC * bz + (size_t)r0 * ldc + cc) = __halves2half2(h0, h1);
                *reinterpret_cast<f162*>(Cl + (size_t)strC * bz + (size_t)r0 * ldc + cc) = __halves2half2(l0, l1);
                split1(v[2], h0, l0); split1(v[3], h1, l1);
                *reinterpret_cast<f162*>(Ch + (size_t)strC * bz + (size_t)r1 * ldc + cc) = __halves2half2(h0, h1);
                *reinterpret_cast<f162*>(Cl + (size_t)strC * bz + (size_t)r1 * ldc + cc) = __halves2half2(l0, l1);
            } else {  // EPI 3, 5: hi only
                *reinterpret_cast<f162*>(Ch + (size_t)strC * bz + (size_t)r0 * ldc + cc) =
                    __halves2half2(__float2half_rn(v[0]), __float2half_rn(v[1]));
                *reinterpret_cast<f162*>(Ch + (size_t)strC * bz + (size_t)r1 * ldc + cc) =
                    __halves2half2(__float2half_rn(v[2]), __float2half_rn(v[3]));
            }
        }
    }
}

// ---------------- LayerNorm -> fp16 hi ----------------
__global__ void __launch_bounds__(256) ln_hi_kernel(
    const float* __restrict__ x, const float* __restrict__ g,
    const float* __restrict__ b, f16* __restrict__ yh)
{
    const size_t row = blockIdx.x;
    const float4 v = reinterpret_cast<const float4*>(x + row * HDIM)[threadIdx.x];
    float s  = v.x + v.y + v.z + v.w;
    float ss = v.x * v.x + v.y * v.y + v.z * v.z + v.w * v.w;

    __shared__ float sm_s[8], sm_ss[8];
    #pragma unroll
    for (int o = 16; o; o >>= 1) {
        s  += __shfl_xor_sync(0xffffffffu, s,  o);
        ss += __shfl_xor_sync(0xffffffffu, ss, o);
    }
    if ((threadIdx.x & 31) == 0) { sm_s[threadIdx.x >> 5] = s; sm_ss[threadIdx.x >> 5] = ss; }
    __syncthreads();
    if (threadIdx.x < 32) {
        float ws  = (threadIdx.x < 8) ? sm_s [threadIdx.x] : 0.0f;
        float wss = (threadIdx.x < 8) ? sm_ss[threadIdx.x] : 0.0f;
        #pragma unroll
        for (int o = 4; o; o >>= 1) {
            ws  += __shfl_xor_sync(0xffffffffu, ws,  o);
            wss += __shfl_xor_sync(0xffffffffu, wss, o);
        }
        if (threadIdx.x == 0) { sm_s[0] = ws; sm_ss[0] = wss; }
    }
    __syncthreads();

    const float mu  = sm_s[0]  * (1.0f / HDIM);
    const float var = sm_ss[0] * (1.0f / HDIM) - mu * mu;
    const float rs  = rsqrtf(var + 1e-5f);

    const float4 gv = reinterpret_cast<const float4*>(g)[threadIdx.x];
    const float4 bv = reinterpret_cast<const float4*>(b)[threadIdx.x];
    const size_t off = row * HDIM + (size_t)threadIdx.x * 4;
    *reinterpret_cast<f162*>(yh + off) = __halves2half2(
        __float2half_rn((v.x - mu) * rs * gv.x + bv.x),
        __float2half_rn((v.y - mu) * rs * gv.y + bv.y));
    *reinterpret_cast<f162*>(yh + off + 2) = __halves2half2(
        __float2half_rn((v.z - mu) * rs * gv.z + bv.z),
        __float2half_rn((v.w - mu) * rs * gv.w + bv.w));
}

// ---------------- Softmax (2048) fp32 -> fp16 hi ----------------
__global__ void __launch_bounds__(256) softmax_hi_kernel(
    const float* __restrict__ s, f16* __restrict__ ph)
{
    const size_t row = blockIdx.x;
    const float4* r = reinterpret_cast<const float4*>(s) + row * (NSEQ / 4);
    const int t = threadIdx.x;
    const float4 a = r[t];
    const float4 c = r[t + 256];
    float vals[8] = {a.x, a.y, a.z, a.w, c.x, c.y, c.z, c.w};

    __shared__ float sm[8];
    float m = vals[0];
    #pragma unroll
    for (int i = 1; i < 8; i++) m = fmaxf(m, vals[i]);
    #pragma unroll
    for (int o = 16; o; o >>= 1) m = fmaxf(m, __shfl_xor_sync(0xffffffffu, m, o));
    if ((t & 31) == 0) sm[t >> 5] = m;
    __syncthreads();
    if (t < 32) {
        float w = (t < 8) ? sm[t] : -INFINITY;
        #pragma unroll
        for (int o = 4; o; o >>= 1) w = fmaxf(w, __shfl_xor_sync(0xffffffffu, w, o));
        if (t == 0) sm[0] = w;
    }
    __syncthreads();
    m = sm[0];
    __syncthreads();

    float sum = 0.0f;
    #pragma unroll
    for (int i = 0; i < 8; i++) { vals[i] = expf(vals[i] - m); sum += vals[i]; }
    #pragma unroll
    for (int o = 16; o; o >>= 1) sum += __shfl_xor_sync(0xffffffffu, sum, o);
    if ((t & 31) == 0) sm[t >> 5] = sum;
    __syncthreads();
    if (t < 32) {
        float w = (t < 8) ? sm[t] : 0.0f;
        #pragma unroll
        for (int o = 4; o; o >>= 1) w += __shfl_xor_sync(0xffffffffu, w, o);
        if (t == 0) sm[0] = w;
    }
    __syncthreads();
    const float inv = 1.0f / sm[0];

    const size_t base = row * NSEQ;
    #pragma unroll
    for (int half = 0; half < 2; half++) {
        const size_t off = base + (size_t)(t + half * 256) * 4;
        const int v0 = half * 4;
        *reinterpret_cast<f162*>(ph + off) = __halves2half2(
            __float2half_rn(vals[v0 + 0] * inv), __float2half_rn(vals[v0 + 1] * inv));
        *reinterpret_cast<f162*>(ph + off + 2) = __halves2half2(
            __float2half_rn(vals[v0 + 2] * inv), __float2half_rn(vals[v0 + 3] * inv));
    }
}

// ---------------- fp32 W[R,C] -> split-fp16 W^T[C,R] ----------------
__global__ void __launch_bounds__(256) wsplit_t_kernel(
    const float* __restrict__ W, int R, int C,
    f16* __restrict__ Th, f16* __restrict__ Tl)
{
    __shared__ float t[32][33];
    const int bx = blockIdx.x * 32;   // C
    const int by = blockIdx.y * 32;   // R
    const int tx = threadIdx.x, ty = threadIdx.y;
    #pragma unroll
    for (int i = 0; i < 4; i++)
        t[ty + i * 8][tx] = W[(size_t)(by + ty + i * 8) * C + bx + tx];
    __syncthreads();
    #pragma unroll
    for (int i = 0; i < 4; i++) {
        const float v = t[tx][ty + i * 8];
        const size_t o = (size_t)(bx + ty + i * 8) * R + by + tx;
        f16 h, l;
        split1(v, h, l);
        Th[o] = h;
        Tl[o] = l;
    }
}

// ---------------- V hi/lo [B][NSEQ,H] -> Vt hi/lo [B][H,NSEQ] ----------------
__global__ void __launch_bounds__(256) vtrans_kernel(
    const f16* __restrict__ vh, const f16* __restrict__ vl,
    f16* __restrict__ vth, f16* __restrict__ vtl)
{
    const int z = blockIdx.z;
    const int b = z >> 1;
    const bool lo = z & 1;
    const f16* src = (lo ? vl : vh) + (size_t)b * NSEQ * HDIM;
    f16* dst       = (lo ? vtl : vth) + (size_t)b * HDIM * NSEQ;

    __shared__ f16 t[32][33];
    const int bx = blockIdx.x * 32;   // H
    const int by = blockIdx.y * 32;   // NSEQ
    const int tx = threadIdx.x, ty = threadIdx.y;
    #pragma unroll
    for (int i = 0; i < 4; i++)
        t[ty + i * 8][tx] = src[(size_t)(by + ty + i * 8) * HDIM + bx + tx];
    __syncthreads();
    #pragma unroll
    for (int i = 0; i < 4; i++)
        dst[(size_t)(bx + ty + i * 8) * NSEQ + by + tx] = t[tx][ty + i * 8];
}

// ---------------------------------------------------------------------------
// kernel_launch — inputs: 0:x 1:ln1_g 2:ln1_b 3:Wq 4:Wk 5:Wv 6:ln2_g 7:ln2_b
//                         8:W1 9:b1 10:W2 11:b2
// ---------------------------------------------------------------------------
extern "C" void kernel_launch(void* const* d_in, const int*, int,
                              void* d_out, int)
{
    const float* x     = (const float*)d_in[0];
    const float* ln1_g = (const float*)d_in[1];
    const float* ln1_b = (const float*)d_in[2];
    const float* Wq    = (const float*)d_in[3];
    const float* Wk    = (const float*)d_in[4];
    const float* Wv    = (const float*)d_in[5];
    const float* ln2_g = (const float*)d_in[6];
    const float* ln2_b = (const float*)d_in[7];
    const float* W1    = (const float*)d_in[8];
    const float* b1    = (const float*)d_in[9];
    const float* W2    = (const float*)d_in[10];
    const float* b2    = (const float*)d_in[11];
    float* out = (float*)d_out;

    f16 *lnh, *qh, *kh, *kl, *vh, *vl, *vth, *vtl, *ph, *hh;
    f16 *wqh, *wql, *wkh, *wkl, *wvh, *wvl, *w1h, *w1l, *w2h, *w2l;
    float *s, *x1;
    cudaGetSymbolAddress((void**)&lnh, g_lnh);
    cudaGetSymbolAddress((void**)&qh, g_qh);
    cudaGetSymbolAddress((void**)&kh, g_kh);   cudaGetSymbolAddress((void**)&kl, g_kl);
    cudaGetSymbolAddress((void**)&vh, g_vh);   cudaGetSymbolAddress((void**)&vl, g_vl);
    cudaGetSymbolAddress((void**)&vth, g_vth); cudaGetSymbolAddress((void**)&vtl, g_vtl);
    cudaGetSymbolAddress((void**)&ph, g_ph);
    cudaGetSymbolAddress((void**)&hh, g_hh);
    cudaGetSymbolAddress((void**)&wqh, g_wqh); cudaGetSymbolAddress((void**)&wql, g_wql);
    cudaGetSymbolAddress((void**)&wkh, g_wkh); cudaGetSymbolAddress((void**)&wkl, g_wkl);
    cudaGetSymbolAddress((void**)&wvh, g_wvh); cudaGetSymbolAddress((void**)&wvl, g_wvl);
    cudaGetSymbolAddress((void**)&w1h, g_w1h); cudaGetSymbolAddress((void**)&w1l, g_w1l);
    cudaGetSymbolAddress((void**)&w2h, g_w2h); cudaGetSymbolAddress((void**)&w2l, g_w2l);
    cudaGetSymbolAddress((void**)&s, g_s);     cudaGetSymbolAddress((void**)&x1, g_x1);

    cudaFuncSetAttribute(mm_kernel<0>, cudaFuncAttributeMaxDynamicSharedMemorySize, MM_SMEM);
    cudaFuncSetAttribute(mm_kernel<1>, cudaFuncAttributeMaxDynamicSharedMemorySize, MM_SMEM);
    cudaFuncSetAttribute(mm_kernel<2>, cudaFuncAttributeMaxDynamicSharedMemorySize, MM_SMEM);
    cudaFuncSetAttribute(mm_kernel<3>, cudaFuncAttributeMaxDynamicSharedMemorySize, MM_SMEM);
    cudaFuncSetAttribute(mm_kernel<4>, cudaFuncAttributeMaxDynamicSharedMemorySize, MM_SMEM);
    cudaFuncSetAttribute(mm_kernel<5>, cudaFuncAttributeMaxDynamicSharedMemorySize, MM_SMEM);

    const long long sNH = (long long)NSEQ * HDIM;
    const long long sNN = (long long)NSEQ * NSEQ;
    dim3 wb(32, 8);

    // launches 0-3: LN1, Wq/Wk/Wv splits
    ln_hi_kernel<<<MTOT, 256>>>(x, ln1_g, ln1_b, lnh);
    wsplit_t_kernel<<<dim3(HDIM/32, HDIM/32), wb>>>(Wq, HDIM, HDIM, wqh, wql);
    wsplit_t_kernel<<<dim3(HDIM/32, HDIM/32), wb>>>(Wk, HDIM, HDIM, wkh, wkl);
    wsplit_t_kernel<<<dim3(HDIM/32, HDIM/32), wb>>>(Wv, HDIM, HDIM, wvh, wvl);

    // 4-6: QKV (launch #5 = K GEMM -> ncu target)
    { dim3 g(HDIM/128, MTOT/128);
      mm_kernel<5><<<g, 256, MM_SMEM>>>(lnh, wqh, wql, HDIM, 0, 0, 0, HDIM,
                                        1.0f, nullptr, nullptr, nullptr, 0, qh, nullptr);
      mm_kernel<1><<<g, 256, MM_SMEM>>>(lnh, wkh, wkl, HDIM, 0, 0, 0, HDIM,
                                        1.0f, nullptr, nullptr, nullptr, 0, kh, kl);
      mm_kernel<1><<<g, 256, MM_SMEM>>>(lnh, wvh, wvl, HDIM, 0, 0, 0, HDIM,
                                        1.0f, nullptr, nullptr, nullptr, 0, vh, vl); }

    // scores = (Q @ K^T)/32, fp32
    { dim3 g(NSEQ/128, NSEQ/128, BATCH);
      mm_kernel<0><<<g, 256, MM_SMEM>>>(qh, kh, kl, HDIM, sNH, sNH, sNN, NSEQ,
                                        0.03125f, s, nullptr, nullptr, 0, nullptr, nullptr); }

    // softmax -> probs hi
    softmax_hi_kernel<<<BATCH * NSEQ, 256>>>(s, ph);

    // V^T per batch (hi/lo planes)
    vtrans_kernel<<<dim3(HDIM/32, NSEQ/32, BATCH * 2), dim3(32, 8)>>>(vh, vl, vth, vtl);

    // x1 = x + P @ V
    { dim3 g(HDIM/128, NSEQ/128, BATCH);
      mm_kernel<2><<<g, 256, MM_SMEM>>>(ph, vth, vtl, NSEQ, sNN, sNH, sNH, HDIM,
                                        1.0f, x1, nullptr, x, sNH, nullptr, nullptr); }

    // LN2 -> hi
    ln_hi_kernel<<<MTOT, 256>>>(x1, ln2_g, ln2_b, lnh);

    // h = gelu(ln @ W1 + b1) -> hi only
    wsplit_t_kernel<<<dim3(FDIM/32, HDIM/32), wb>>>(W1, HDIM, FDIM, w1h, w1l);
    { dim3 g(FDIM/128, MTOT/128);
      mm_kernel<3><<<g, 256, MM_SMEM>>>(lnh, w1h, w1l, HDIM, 0, 0, 0, FDIM,
                                        1.0f, nullptr, b1, nullptr, 0, hh, nullptr); }

    // out = x1 + h @ W2 + b2
    wsplit_t_kernel<<<dim3(HDIM/32, FDIM/32), wb>>>(W2, FDIM, HDIM, w2h, w2l);
    { dim3 g(HDIM/128, MTOT/128);
      mm_kernel<4><<<g, 256, MM_SMEM>>>(hh, w2h, w2l, FDIM, 0, 0, 0, HDIM,
                                        1.0f, out, b2, x1, 0, nullptr, nullptr); }
}

// round 10
// speedup vs baseline: 6.2671x; 1.6056x over previous
#include <cuda_runtime.h>
#include <cuda_fp16.h>
#include <math.h>
#include <stdint.h>

#define BATCH 8
#define NSEQ  2048
#define HDIM  1024
#define FDIM  4096
#define MTOT  (BATCH * NSEQ)

typedef __half  f16;
typedef __half2 f162;

// ---------------- scratch (__device__ globals; allocation-free) ----------------
static __device__ __align__(16) f16   g_lnh[(size_t)MTOT * HDIM];   // LN out
static __device__ __align__(16) f16   g_qh [(size_t)MTOT * HDIM];   // Q
static __device__ __align__(16) f16   g_kh [(size_t)MTOT * HDIM];   // K
static __device__ __align__(16) f16   g_vh [(size_t)MTOT * HDIM];   // V
static __device__ __align__(16) f16   g_vth[(size_t)MTOT * HDIM];   // V^T
static __device__ __align__(16) float g_s  [(size_t)BATCH * NSEQ * NSEQ];
static __device__ __align__(16) f16   g_ph [(size_t)BATCH * NSEQ * NSEQ];  // probs
static __device__ __align__(16) float g_x1 [(size_t)MTOT * HDIM];
static __device__ __align__(16) f16   g_hh [(size_t)MTOT * FDIM];   // FFN hidden
static __device__ __align__(16) f16   g_wqh[(size_t)HDIM * HDIM];
static __device__ __align__(16) f16   g_wkh[(size_t)HDIM * HDIM];
static __device__ __align__(16) f16   g_wvh[(size_t)HDIM * HDIM];
static __device__ __align__(16) f16   g_w1h[(size_t)FDIM * HDIM];
static __device__ __align__(16) f16   g_w2h[(size_t)HDIM * FDIM];

// ---------------- helpers ----------------
__device__ __forceinline__ uint32_t smem_u32(const void* p) {
    uint32_t a;
    asm("{ .reg .u64 t; cvta.to.shared.u64 t, %1; cvt.u32.u64 %0, t; }" : "=r"(a) : "l"(p));
    return a;
}
__device__ __forceinline__ void cpa16(uint32_t dst, const f16* src) {
    asm volatile("cp.async.cg.shared.global [%0], [%1], 16;" :: "r"(dst), "l"(src));
}
__device__ __forceinline__ void cp_commit() { asm volatile("cp.async.commit_group;" ::: "memory"); }
__device__ __forceinline__ void ldm4(uint32_t* a, uint32_t addr) {
    asm volatile("ldmatrix.sync.aligned.m8n8.x4.shared.b16 {%0,%1,%2,%3}, [%4];"
                 : "=r"(a[0]), "=r"(a[1]), "=r"(a[2]), "=r"(a[3]) : "r"(addr));
}
__device__ __forceinline__ void mma16816(float* d, const uint32_t* a, const uint32_t* b) {
    asm volatile(
        "mma.sync.aligned.m16n8k16.row.col.f32.f16.f16.f32 "
        "{%0,%1,%2,%3}, {%4,%5,%6,%7}, {%8,%9}, {%0,%1,%2,%3};"
        : "+f"(d[0]), "+f"(d[1]), "+f"(d[2]), "+f"(d[3])
        : "r"(a[0]), "r"(a[1]), "r"(a[2]), "r"(a[3]), "r"(b[0]), "r"(b[1]));
}
__device__ __forceinline__ float gelu_exact(float x) {
    return 0.5f * x * (1.0f + erff(x * 0.70710678118654752440f));
}

// ---------------------------------------------------------------------------
// fp16 mma.sync GEMM: C = alpha*(A @ B^T) (+epilogue)
// A:[M,K], B:[N,K] fp16, K-major. Block 128x128, kchunk 32, 256 thr,
// warp tile 64x32, fp32 accum, 2 CTAs/SM, double-buffered cp.async.
// smem: 2 stages x 2 planes x (128 rows x 80B) = 40960 B.
// EPI: 0 Cf=alpha*acc | 2 Cf=acc+res | 3 Ch=gelu(acc+bias) |
//      4 Cf=acc+bias+res | 5 Ch=acc
// ---------------------------------------------------------------------------
#define PLANE   10240
#define BUFSZ   (2 * PLANE)
#define MM_SMEM (2 * BUFSZ)

template<int EPI>
__global__ void __launch_bounds__(256, 2) mm_kernel(
    const f16* __restrict__ Ah,
    const f16* __restrict__ Bh,
    int K, long long strA, long long strB, long long strC,
    int ldc, float alpha,
    float* __restrict__ Cf, const float* __restrict__ bias,
    const float* __restrict__ res, long long strRes,
    f16* __restrict__ Ch)
{
    extern __shared__ __align__(16) char smem[];
    const uint32_t su = smem_u32(smem);
    const int tid  = threadIdx.x;
    const int lane = tid & 31;
    const int warp = tid >> 5;
    const int bz   = blockIdx.z;
    const int bm   = blockIdx.y * 128;
    const int bn   = blockIdx.x * 128;

    Ah += (size_t)strA * bz;
    Bh += (size_t)strB * bz;

    // loader mapping: idx in [0,512): row = idx>>2, 16B-chunk = idx&3
    const int i0 = tid, i1 = tid + 256;
    const int r0l = i0 >> 2, c0l = i0 & 3;
    const int r1l = i1 >> 2, c1l = i1 & 3;
    const uint32_t d0 = (uint32_t)(r0l * 80 + c0l * 16);
    const uint32_t d1 = (uint32_t)(r1l * 80 + c1l * 16);
    const size_t gA0 = (size_t)(bm + r0l) * K + c0l * 8;
    const size_t gA1 = (size_t)(bm + r1l) * K + c1l * 8;
    const size_t gB0 = (size_t)(bn + r0l) * K + c0l * 8;
    const size_t gB1 = (size_t)(bn + r1l) * K + c1l * 8;

    const int nch = K >> 5;

    // warp tile: 2 (m) x 4 (n)
    const int wm = (warp & 1) * 64;
    const int wn = (warp >> 1) * 32;

    float acc[4][4][4];
    #pragma unroll
    for (int i = 0; i < 4; i++)
        #pragma unroll
        for (int j = 0; j < 4; j++)
            #pragma unroll
            for (int r = 0; r < 4; r++) acc[i][j][r] = 0.0f;

    // A ldmatrix lane address components
    const int arow = lane & 15;
    const int acol = (lane >> 4) * 16;               // bytes
    // B ldmatrix lane address components
    const int bg   = lane >> 3;                      // 0..3 (matrix group)
    const int br   = lane & 7;
    const uint32_t boff = (uint32_t)(((bg >> 1) * 8 + br) * 80 + (bg & 1) * 16);

    // prologue: chunk 0 -> buf 0
    {
        uint32_t b = su;
        cpa16(b + d0,         Ah + gA0);  cpa16(b + d1,         Ah + gA1);
        cpa16(b + PLANE + d0, Bh + gB0);  cpa16(b + PLANE + d1, Bh + gB1);
        cp_commit();
    }

    for (int c = 0; c < nch; c++) {
        if (c + 1 < nch) {
            const size_t k0 = (size_t)(c + 1) << 5;
            uint32_t b = su + ((c + 1) & 1) * BUFSZ;
            cpa16(b + d0,         Ah + gA0 + k0);  cpa16(b + d1,         Ah + gA1 + k0);
            cpa16(b + PLANE + d0, Bh + gB0 + k0);  cpa16(b + PLANE + d1, Bh + gB1 + k0);
            cp_commit();
            asm volatile("cp.async.wait_group 1;" ::: "memory");
        } else {
            asm volatile("cp.async.wait_group 0;" ::: "memory");
        }
        __syncthreads();

        const uint32_t bb = su + (c & 1) * BUFSZ;

        #pragma unroll
        for (int ks = 0; ks < 2; ks++) {
            uint32_t a[4][4], bH[4][2];
            #pragma unroll
            for (int i = 0; i < 4; i++)
                ldm4(a[i], bb + (uint32_t)((wm + i * 16 + arow) * 80 + ks * 32 + acol));
            #pragma unroll
            for (int p = 0; p < 2; p++) {
                uint32_t r[4];
                ldm4(r, bb + PLANE + (uint32_t)((wn + p * 16) * 80 + ks * 32) + boff);
                bH[p*2+0][0] = r[0]; bH[p*2+0][1] = r[1];
                bH[p*2+1][0] = r[2]; bH[p*2+1][1] = r[3];
            }
            #pragma unroll
            for (int i = 0; i < 4; i++)
                #pragma unroll
                for (int j = 0; j < 4; j++) mma16816(acc[i][j], a[i], bH[j]);
        }
        __syncthreads();
    }

    // -------- epilogue --------
    #pragma unroll
    for (int i = 0; i < 4; i++) {
        #pragma unroll
        for (int j = 0; j < 4; j++) {
            const int r0 = bm + wm + i * 16 + (lane >> 2);
            const int r1 = r0 + 8;
            const int cc = bn + wn + j * 8 + (lane & 3) * 2;
            float v[4] = {acc[i][j][0], acc[i][j][1], acc[i][j][2], acc[i][j][3]};

            if constexpr (EPI == 0) {
                v[0] *= alpha; v[1] *= alpha; v[2] *= alpha; v[3] *= alpha;
            }
            if constexpr (EPI == 3 || EPI == 4) {
                const float2 bbv = *reinterpret_cast<const float2*>(bias + cc);
                v[0] += bbv.x; v[1] += bbv.y; v[2] += bbv.x; v[3] += bbv.y;
            }
            if constexpr (EPI == 3) {
                v[0] = gelu_exact(v[0]); v[1] = gelu_exact(v[1]);
                v[2] = gelu_exact(v[2]); v[3] = gelu_exact(v[3]);
            }
            if constexpr (EPI == 2 || EPI == 4) {
                const float* rp = res + (size_t)strRes * bz;
                const float2 q0 = *reinterpret_cast<const float2*>(rp + (size_t)r0 * ldc + cc);
                const float2 q1 = *reinterpret_cast<const float2*>(rp + (size_t)r1 * ldc + cc);
                v[0] += q0.x; v[1] += q0.y; v[2] += q1.x; v[3] += q1.y;
            }

            if constexpr (EPI == 0 || EPI == 2 || EPI == 4) {
                float* cp0 = Cf + (size_t)strC * bz + (size_t)r0 * ldc + cc;
                float* cp1 = Cf + (size_t)strC * bz + (size_t)r1 * ldc + cc;
                *reinterpret_cast<float2*>(cp0) = make_float2(v[0], v[1]);
                *reinterpret_cast<float2*>(cp1) = make_float2(v[2], v[3]);
            } else {  // EPI 3, 5: fp16 out
                *reinterpret_cast<f162*>(Ch + (size_t)strC * bz + (size_t)r0 * ldc + cc) =
                    __halves2half2(__float2half_rn(v[0]), __float2half_rn(v[1]));
                *reinterpret_cast<f162*>(Ch + (size_t)strC * bz + (size_t)r1 * ldc + cc) =
                    __halves2half2(__float2half_rn(v[2]), __float2half_rn(v[3]));
            }
        }
    }
}

// ---------------- LayerNorm -> fp16 ----------------
__global__ void __launch_bounds__(256) ln_hi_kernel(
    const float* __restrict__ x, const float* __restrict__ g,
    const float* __restrict__ b, f16* __restrict__ yh)
{
    const size_t row = blockIdx.x;
    const float4 v = reinterpret_cast<const float4*>(x + row * HDIM)[threadIdx.x];
    float s  = v.x + v.y + v.z + v.w;
    float ss = v.x * v.x + v.y * v.y + v.z * v.z + v.w * v.w;

    __shared__ float sm_s[8], sm_ss[8];
    #pragma unroll
    for (int o = 16; o; o >>= 1) {
        s  += __shfl_xor_sync(0xffffffffu, s,  o);
        ss += __shfl_xor_sync(0xffffffffu, ss, o);
    }
    if ((threadIdx.x & 31) == 0) { sm_s[threadIdx.x >> 5] = s; sm_ss[threadIdx.x >> 5] = ss; }
    __syncthreads();
    if (threadIdx.x < 32) {
        float ws  = (threadIdx.x < 8) ? sm_s [threadIdx.x] : 0.0f;
        float wss = (threadIdx.x < 8) ? sm_ss[threadIdx.x] : 0.0f;
        #pragma unroll
        for (int o = 4; o; o >>= 1) {
            ws  += __shfl_xor_sync(0xffffffffu, ws,  o);
            wss += __shfl_xor_sync(0xffffffffu, wss, o);
        }
        if (threadIdx.x == 0) { sm_s[0] = ws; sm_ss[0] = wss; }
    }
    __syncthreads();

    const float mu  = sm_s[0]  * (1.0f / HDIM);
    const float var = sm_ss[0] * (1.0f / HDIM) - mu * mu;
    const float rs  = rsqrtf(var + 1e-5f);

    const float4 gv = reinterpret_cast<const float4*>(g)[threadIdx.x];
    const float4 bv = reinterpret_cast<const float4*>(b)[threadIdx.x];
    const size_t off = row * HDIM + (size_t)threadIdx.x * 4;
    *reinterpret_cast<f162*>(yh + off) = __halves2half2(
        __float2half_rn((v.x - mu) * rs * gv.x + bv.x),
        __float2half_rn((v.y - mu) * rs * gv.y + bv.y));
    *reinterpret_cast<f162*>(yh + off + 2) = __halves2half2(
        __float2half_rn((v.z - mu) * rs * gv.z + bv.z),
        __float2half_rn((v.w - mu) * rs * gv.w + bv.w));
}

// ---------------- Softmax (2048) fp32 -> fp16 ----------------
__global__ void __launch_bounds__(256) softmax_hi_kernel(
    const float* __restrict__ s, f16* __restrict__ ph)
{
    const size_t row = blockIdx.x;
    const float4* r = reinterpret_cast<const float4*>(s) + row * (NSEQ / 4);
    const int t = threadIdx.x;
    const float4 a = r[t];
    const float4 c = r[t + 256];
    float vals[8] = {a.x, a.y, a.z, a.w, c.x, c.y, c.z, c.w};

    __shared__ float sm[8];
    float m = vals[0];
    #pragma unroll
    for (int i = 1; i < 8; i++) m = fmaxf(m, vals[i]);
    #pragma unroll
    for (int o = 16; o; o >>= 1) m = fmaxf(m, __shfl_xor_sync(0xffffffffu, m, o));
    if ((t & 31) == 0) sm[t >> 5] = m;
    __syncthreads();
    if (t < 32) {
        float w = (t < 8) ? sm[t] : -INFINITY;
        #pragma unroll
        for (int o = 4; o; o >>= 1) w = fmaxf(w, __shfl_xor_sync(0xffffffffu, w, o));
        if (t == 0) sm[0] = w;
    }
    __syncthreads();
    m = sm[0];
    __syncthreads();

    float sum = 0.0f;
    #pragma unroll
    for (int i = 0; i < 8; i++) { vals[i] = expf(vals[i] - m); sum += vals[i]; }
    #pragma unroll
    for (int o = 16; o; o >>= 1) sum += __shfl_xor_sync(0xffffffffu, sum, o);
    if ((t & 31) == 0) sm[t >> 5] = sum;
    __syncthreads();
    if (t < 32) {
        float w = (t < 8) ? sm[t] : 0.0f;
        #pragma unroll
        for (int o = 4; o; o >>= 1) w += __shfl_xor_sync(0xffffffffu, w, o);
        if (t == 0) sm[0] = w;
    }
    __syncthreads();
    const float inv = 1.0f / sm[0];

    const size_t base = row * NSEQ;
    #pragma unroll
    for (int half = 0; half < 2; half++) {
        const size_t off = base + (size_t)(t + half * 256) * 4;
        const int v0 = half * 4;
        *reinterpret_cast<f162*>(ph + off) = __halves2half2(
            __float2half_rn(vals[v0 + 0] * inv), __float2half_rn(vals[v0 + 1] * inv));
        *reinterpret_cast<f162*>(ph + off + 2) = __halves2half2(
            __float2half_rn(vals[v0 + 2] * inv), __float2half_rn(vals[v0 + 3] * inv));
    }
}

// ---------------- fp32 W[R,C] -> fp16 W^T[C,R] ----------------
__global__ void __launch_bounds__(256) wcast_t_kernel(
    const float* __restrict__ W, int R, int C, f16* __restrict__ Th)
{
    __shared__ float t[32][33];
    const int bx = blockIdx.x * 32;   // C
    const int by = blockIdx.y * 32;   // R
    const int tx = threadIdx.x, ty = threadIdx.y;
    #pragma unroll
    for (int i = 0; i < 4; i++)
        t[ty + i * 8][tx] = W[(size_t)(by + ty + i * 8) * C + bx + tx];
    __syncthreads();
    #pragma unroll
    for (int i = 0; i < 4; i++)
        Th[(size_t)(bx + ty + i * 8) * R + by + tx] = __float2half_rn(t[tx][ty + i * 8]);
}

// ---------------- V [B][NSEQ,H] -> Vt [B][H,NSEQ] ----------------
__global__ void __launch_bounds__(256) vtrans_kernel(
    const f16* __restrict__ vh, f16* __restrict__ vth)
{
    const int b = blockIdx.z;
    const f16* src = vh + (size_t)b * NSEQ * HDIM;
    f16* dst       = vth + (size_t)b * HDIM * NSEQ;

    __shared__ f16 t[32][33];
    const int bx = blockIdx.x * 32;   // H
    const int by = blockIdx.y * 32;   // NSEQ
    const int tx = threadIdx.x, ty = threadIdx.y;
    #pragma unroll
    for (int i = 0; i < 4; i++)
        t[ty + i * 8][tx] = src[(size_t)(by + ty + i * 8) * HDIM + bx + tx];
    __syncthreads();
    #pragma unroll
    for (int i = 0; i < 4; i++)
        dst[(size_t)(bx + ty + i * 8) * NSEQ + by + tx] = t[tx][ty + i * 8];
}

// ---------------------------------------------------------------------------
// kernel_launch — inputs: 0:x 1:ln1_g 2:ln1_b 3:Wq 4:Wk 5:Wv 6:ln2_g 7:ln2_b
//                         8:W1 9:b1 10:W2 11:b2
// ---------------------------------------------------------------------------
extern "C" void kernel_launch(void* const* d_in, const int*, int,
                              void* d_out, int)
{
    const float* x     = (const float*)d_in[0];
    const float* ln1_g = (const float*)d_in[1];
    const float* ln1_b = (const float*)d_in[2];
    const float* Wq    = (const float*)d_in[3];
    const float* Wk    = (const float*)d_in[4];
    const float* Wv    = (const float*)d_in[5];
    const float* ln2_g = (const float*)d_in[6];
    const float* ln2_b = (const float*)d_in[7];
    const float* W1    = (const float*)d_in[8];
    const float* b1    = (const float*)d_in[9];
    const float* W2    = (const float*)d_in[10];
    const float* b2    = (const float*)d_in[11];
    float* out = (float*)d_out;

    f16 *lnh, *qh, *kh, *vh, *vth, *ph, *hh, *wqh, *wkh, *wvh, *w1h, *w2h;
    float *s, *x1;
    cudaGetSymbolAddress((void**)&lnh, g_lnh);
    cudaGetSymbolAddress((void**)&qh, g_qh);
    cudaGetSymbolAddress((void**)&kh, g_kh);
    cudaGetSymbolAddress((void**)&vh, g_vh);
    cudaGetSymbolAddress((void**)&vth, g_vth);
    cudaGetSymbolAddress((void**)&ph, g_ph);
    cudaGetSymbolAddress((void**)&hh, g_hh);
    cudaGetSymbolAddress((void**)&wqh, g_wqh);
    cudaGetSymbolAddress((void**)&wkh, g_wkh);
    cudaGetSymbolAddress((void**)&wvh, g_wvh);
    cudaGetSymbolAddress((void**)&w1h, g_w1h);
    cudaGetSymbolAddress((void**)&w2h, g_w2h);
    cudaGetSymbolAddress((void**)&s, g_s);
    cudaGetSymbolAddress((void**)&x1, g_x1);

    cudaFuncSetAttribute(mm_kernel<0>, cudaFuncAttributeMaxDynamicSharedMemorySize, MM_SMEM);
    cudaFuncSetAttribute(mm_kernel<2>, cudaFuncAttributeMaxDynamicSharedMemorySize, MM_SMEM);
    cudaFuncSetAttribute(mm_kernel<3>, cudaFuncAttributeMaxDynamicSharedMemorySize, MM_SMEM);
    cudaFuncSetAttribute(mm_kernel<4>, cudaFuncAttributeMaxDynamicSharedMemorySize, MM_SMEM);
    cudaFuncSetAttribute(mm_kernel<5>, cudaFuncAttributeMaxDynamicSharedMemorySize, MM_SMEM);

    const long long sNH = (long long)NSEQ * HDIM;
    const long long sNN = (long long)NSEQ * NSEQ;
    dim3 wb(32, 8);

    // LN1 + weight casts
    ln_hi_kernel<<<MTOT, 256>>>(x, ln1_g, ln1_b, lnh);
    wcast_t_kernel<<<dim3(HDIM/32, HDIM/32), wb>>>(Wq, HDIM, HDIM, wqh);
    wcast_t_kernel<<<dim3(HDIM/32, HDIM/32), wb>>>(Wk, HDIM, HDIM, wkh);
    wcast_t_kernel<<<dim3(HDIM/32, HDIM/32), wb>>>(Wv, HDIM, HDIM, wvh);

    // QKV (M=16384, N=1024, K=1024)   [launches 4,5,6 — ncu -s 5 lands here]
    { dim3 g(HDIM/128, MTOT/128);
      mm_kernel<5><<<g, 256, MM_SMEM>>>(lnh, wqh, HDIM, 0, 0, 0, HDIM,
                                        1.0f, nullptr, nullptr, nullptr, 0, qh);
      mm_kernel<5><<<g, 256, MM_SMEM>>>(lnh, wkh, HDIM, 0, 0, 0, HDIM,
                                        1.0f, nullptr, nullptr, nullptr, 0, kh);
      mm_kernel<5><<<g, 256, MM_SMEM>>>(lnh, wvh, HDIM, 0, 0, 0, HDIM,
                                        1.0f, nullptr, nullptr, nullptr, 0, vh); }

    // scores = (Q @ K^T)/32, fp32
    { dim3 g(NSEQ/128, NSEQ/128, BATCH);
      mm_kernel<0><<<g, 256, MM_SMEM>>>(qh, kh, HDIM, sNH, sNH, sNN, NSEQ,
                                        0.03125f, s, nullptr, nullptr, 0, nullptr); }

    // softmax -> probs fp16
    softmax_hi_kernel<<<BATCH * NSEQ, 256>>>(s, ph);

    // V^T per batch
    vtrans_kernel<<<dim3(HDIM/32, NSEQ/32, BATCH), dim3(32, 8)>>>(vh, vth);

    // x1 = x + P @ V
    { dim3 g(HDIM/128, NSEQ/128, BATCH);
      mm_kernel<2><<<g, 256, MM_SMEM>>>(ph, vth, NSEQ, sNN, sNH, sNH, HDIM,
                                        1.0f, x1, nullptr, x, sNH, nullptr); }

    // LN2
    ln_hi_kernel<<<MTOT, 256>>>(x1, ln2_g, ln2_b, lnh);

    // h = gelu(ln @ W1 + b1)
    wcast_t_kernel<<<dim3(FDIM/32, HDIM/32), wb>>>(W1, HDIM, FDIM, w1h);
    { dim3 g(FDIM/128, MTOT/128);
      mm_kernel<3><<<g, 256, MM_SMEM>>>(lnh, w1h, HDIM, 0, 0, 0, FDIM,
                                        1.0f, nullptr, b1, nullptr, 0, hh); }

    // out = x1 + h @ W2 + b2
    wcast_t_kernel<<<dim3(HDIM/32, FDIM/32), wb>>>(W2, FDIM, HDIM, w2h);
    { dim3 g(HDIM/128, MTOT/128);
      mm_kernel<4><<<g, 256, MM_SMEM>>>(hh, w2h, FDIM, 0, 0, 0, HDIM,
                                        1.0f, out, b2, x1, 0, nullptr); }
}